// round 12
// baseline (speedup 1.0000x reference)
#include <cuda_runtime.h>
#include <math.h>

#define KKEY   2048
#define CFEAT  128
#define M_GRID 216
#define NPROP  48
#define NPTS   (NPROP*M_GRID)      // 10368 per batch
#define NTOT   (2*NPTS)            // 20736
#define QDIM   (128*M_GRID)        // 27648
#define KSPLIT 108
#define KCHUNK 256

typedef unsigned long long ull;

__device__ __forceinline__ ull pack2(float lo, float hi) {
    ull r; asm("mov.b64 %0, {%1, %2};" : "=l"(r) : "f"(lo), "f"(hi)); return r;
}
__device__ __forceinline__ ull ffma2(ull a, ull b, ull c) {
    ull d; asm("fma.rn.f32x2 %0, %1, %2, %3;" : "=l"(d) : "l"(a), "l"(b), "l"(c)); return d;
}
__device__ __forceinline__ float2 unpack2(ull v) {
    float2 f; asm("mov.b64 {%0, %1}, %2;" : "=f"(f.x), "=f"(f.y) : "l"(v)); return f;
}
__device__ __forceinline__ unsigned f2tf32(float v) {
    unsigned u; asm("cvt.rna.tf32.f32 %0, %1;" : "=r"(u) : "f"(v)); return u;
}
__device__ __forceinline__ void mma_tf32(float d[4], const unsigned a0, const unsigned a1,
                                         const unsigned a2, const unsigned a3,
                                         const unsigned b0, const unsigned b1) {
    asm("mma.sync.aligned.m16n8k8.row.col.f32.tf32.tf32.f32 "
        "{%0,%1,%2,%3}, {%4,%5,%6,%7}, {%8,%9}, {%0,%1,%2,%3};"
        : "+f"(d[0]), "+f"(d[1]), "+f"(d[2]), "+f"(d[3])
        : "r"(a0), "r"(a1), "r"(a2), "r"(a3), "r"(b0), "r"(b1));
}

// ---------------- scratch ----------------
__device__ float  g_pre[2*2*KKEY*64];        // [scale][b][k][interleaved o]
__device__ float4 g_rel1[NTOT*32];           // {rx,ry,rz, bitcast k}
__device__ float4 g_rel0[NTOT*16];
__device__ float  g_pooled[2*NPROP*QDIM];    // 96 x 27648, q = co*216+mm
__device__ float  g_partial[KSPLIT*96*256];

// ---------------- kernel B: pre[k][o] = W0[:,3:] . feats[:,k] ----------------
__global__ void __launch_bounds__(256) kB(const float* __restrict__ feats,
                                          const float* __restrict__ w0,
                                          const float* __restrict__ w1) {
    __shared__ float Ws[CFEAT*64];
    __shared__ float fs[CFEAT*32];
    int sb = blockIdx.y; int sc = sb >> 1, b = sb & 1;
    const float* W = sc ? w1 : w0;
    for (int i = threadIdx.x; i < CFEAT*64; i += 256) {
        int c = i >> 6, o = i & 63;
        Ws[i] = W[o*131 + 3 + c];
    }
    int kbase = blockIdx.x * 32;
    const float* fb = feats + (size_t)b*CFEAT*KKEY + kbase;
    for (int i = threadIdx.x; i < CFEAT*8; i += 256) {
        int c = i >> 3, q = i & 7;
        *(float4*)(fs + c*32 + q*4) = *(const float4*)(fb + (size_t)c*KKEY + q*4);
    }
    __syncthreads();

    int o  = threadIdx.x & 63;
    int kk = threadIdx.x >> 6;
    ull acc0 = 0, acc1 = 0, acc2 = 0, acc3 = 0;
    #pragma unroll 4
    for (int c = 0; c < CFEAT; c++) {
        float w = Ws[c*64 + o];
        ull wd = pack2(w, w);
        const ull* f = (const ull*)(fs + c*32 + kk*8);
        acc0 = ffma2(wd, f[0], acc0);
        acc1 = ffma2(wd, f[1], acc1);
        acc2 = ffma2(wd, f[2], acc2);
        acc3 = ffma2(wd, f[3], acc3);
    }
    size_t base = ((size_t)(sc*2 + b)*KKEY + kbase + kk*8) << 6;
    int oi = ((o & 31) << 1) + (o >> 5);
    float2 u;
    u = unpack2(acc0); g_pre[base + oi] = u.x; g_pre[base + 64 + oi] = u.y;
    u = unpack2(acc1); g_pre[base + 128 + oi] = u.x; g_pre[base + 192 + oi] = u.y;
    u = unpack2(acc2); g_pre[base + 256 + oi] = u.x; g_pre[base + 320 + oi] = u.y;
    u = unpack2(acc3); g_pre[base + 384 + oi] = u.x; g_pre[base + 448 + oi] = u.y;
}

// ---------------- kernel Q: grid transform + ball query -> rel coords -------
// kA fused: each warp computes its point's xyz inline (uniform broadcast LDGs).
__global__ void __launch_bounds__(512) kQ(const float* __restrict__ prop,
                                          const float* __restrict__ gnoise,
                                          const float* __restrict__ kxyzg) {
    __shared__ float4 kp4[KKEY];               // {x,y,z,|k|^2}, 32KB
    __shared__ int idx1s[16][32], idx0s[16][16];

    const int b = blockIdx.x / 648;
    const float* kb = kxyzg + (size_t)b*KKEY*3;
    for (int i = threadIdx.x; i < KKEY; i += 512) {
        float x = kb[i*3], y = kb[i*3+1], z = kb[i*3+2];
        kp4[i] = make_float4(x, y, z, fmaf(x,x, fmaf(y,y, z*z)));
    }
    __syncthreads();

    const int w = threadIdx.x >> 5, lane = threadIdx.x & 31;
    const int p = blockIdx.x*16 + w;
    const int rp = p % NPTS;
    const int n = rp / M_GRID, mmq = rp % M_GRID;

    // fused kA: xyz of this point (same expressions as original kA)
    const float* p7 = prop + (size_t)(b*NPROP + n)*7;
    const float* gg = gnoise + ((size_t)(b*NPROP + n)*M_GRID + mmq)*3;
    float gx = gg[0]*p7[3], gy = gg[1]*p7[4], gz = gg[2]*p7[5];
    float cth = cosf(p7[6]), sth = sinf(p7[6]);
    const float px = cth*gx - sth*gy + p7[0];
    const float py = sth*gx + cth*gy + p7[1];
    const float pz = gz + p7[2];
    const float pn = fmaf(px,px, fmaf(py,py, pz*pz));

    const float R0 = 0.8f*0.8f, R1 = 1.6f*1.6f;
    int* l1 = idx1s[w];
    int* l0 = idx0s[w];
    int c0 = 0, c1 = 0;
    const unsigned lt = (1u << lane) - 1u;
    for (int base = 0; base < KKEY; base += 32) {
        int k = base + lane;
        float4 kk = kp4[k];
        float dot = fmaf(px,kk.x, fmaf(py,kk.y, pz*kk.z));
        float d2  = fmaf(-2.f, dot, pn + kk.w);
        bool v1 = d2 < R1, v0 = d2 < R0;
        unsigned m1 = __ballot_sync(0xffffffffu, v1);
        unsigned m0 = __ballot_sync(0xffffffffu, v0);
        if ((m1 | m0) == 0u) continue;         // nothing to record this group
        if (c1 < 32 && m1) {
            if (v1) { int rk = c1 + __popc(m1 & lt); if (rk < 32) l1[rk] = k; }
            c1 = min(32, c1 + __popc(m1));
        }
        if (c0 < 16 && m0) {
            if (v0) { int rk = c0 + __popc(m0 & lt); if (rk < 16) l0[rk] = k; }
            c0 = min(16, c0 + __popc(m0));
        }
        if (c0 >= 16 && c1 >= 32) break;
    }
    __syncwarp();
    if (c1 == 0) { if (lane == 0) l1[0] = 0; c1 = 1; }
    if (c0 == 0) { if (lane == 0) l0[0] = 0; c0 = 1; }
    __syncwarp();
    {
        int f1 = l1[0], f0 = l0[0];
        if (lane >= c1) l1[lane] = f1;
        if (lane < 16 && lane >= c0) l0[lane] = f0;
    }
    __syncwarp();

    {
        int k = l1[lane];
        float4 kk = kp4[k];
        g_rel1[(size_t)p*32 + lane] =
            make_float4(kk.x-px, kk.y-py, kk.z-pz, __int_as_float(k));
        if (lane < 16) {
            int k0 = l0[lane];
            float4 k4 = kp4[k0];
            g_rel0[(size_t)p*16 + lane] =
                make_float4(k4.x-px, k4.y-py, k4.z-pz, __int_as_float(k0));
        }
    }
}

// ---------------- kernel C2: 1 pt/warp, 128-bit smem + coalesced epilogue ---
// 384 threads = 12 warps = 12 consecutive points (one n-row, mm0..mm0+11).
// Fragment layouts identical to R11 (validated). New: outputs staged in smem
// [128 o_all][12 w] then written as 384 aligned STG.128 (12-float segments).
// dyn smem words:
//  wpk  0     .. 10240   (2*8*32*10 uint2)
//  wxyz 10240 .. 10624
//  b0s  10624 .. 10752
//  b1s  10752 .. 10880
//  hw   10880 .. 24704   (12 warps * 8 rows * 144)
//  rel  24704 .. 27008   (12 warps * 48 float4)
//  out  27008 .. 28544   (128 * 12)
#define KC2_SMEM_WORDS 28544
#define OFF2_WXYZ 10240
#define OFF2_B0   10624
#define OFF2_B1   10752
#define OFF2_HW   10880
#define OFF2_REL  24704
#define OFF2_OUT  27008
#define HW_PITCH  144

__global__ void __launch_bounds__(384, 2) kC2(
    const float* __restrict__ w00, const float* __restrict__ b00,
    const float* __restrict__ w01, const float* __restrict__ b01,
    const float* __restrict__ w10, const float* __restrict__ b10,
    const float* __restrict__ w11, const float* __restrict__ b11)
{
    extern __shared__ float sm[];
    uint2*    wpk  = (uint2*)sm;               // [sc][kt][lane][nt pad10]
    float*    wxyz = sm + OFF2_WXYZ;
    float*    b0s  = sm + OFF2_B0;
    float*    b1s  = sm + OFF2_B1;
    unsigned* hwg  = (unsigned*)(sm + OFF2_HW);
    float4*   relg = (float4*)(sm + OFF2_REL);
    float*    outs = sm + OFF2_OUT;            // [o_all 0..127][12]

    for (int i = threadIdx.x; i < 2*8*32*8; i += 384) {
        int nt = i & 7, lane2 = (i >> 3) & 31, kt = (i >> 8) & 7, sc = i >> 11;
        int gid2 = lane2 >> 2, tig2 = lane2 & 3;
        const float* W1 = sc ? w11 : w01;
        int o = nt*8 + gid2;
        int j = kt*4 + tig2;
        wpk[sc*2560 + kt*320 + lane2*10 + nt] =
            make_uint2(f2tf32(W1[o*64 + j]), f2tf32(W1[o*64 + j + 32]));
    }
    for (int i = threadIdx.x; i < 2*3*64; i += 384) {
        int sc = i / 192, t = i % 192, d = t / 64, o = t % 64;
        wxyz[i] = (sc ? w10 : w00)[o*131 + d];
    }
    if (threadIdx.x < 256) {
        int sc = (threadIdx.x >> 6) & 1, o = threadIdx.x & 63;
        if (threadIdx.x < 128) b0s[threadIdx.x] = (sc ? b10 : b00)[o];
        else                   b1s[threadIdx.x - 128] = (sc ? b11 : b01)[o];
    }
    __syncthreads();

    const int w = threadIdx.x >> 5, lane = threadIdx.x & 31;
    const int gid = lane >> 2, tig = lane & 3;
    const int p  = blockIdx.x*12 + w;
    const int b  = p / NPTS;

    unsigned* hw = hwg + w*8*HW_PITCH;
    float4*   relw = relg + w*48;
    const int colu = gid*16 + tig*4;

    relw[16 + lane] = g_rel1[(size_t)p*32 + lane];
    if (lane < 16) relw[lane] = g_rel0[(size_t)p*16 + lane];
    __syncwarp();

    #pragma unroll
    for (int sc = 0; sc < 2; sc++) {
        const int NPASS = sc ? 2 : 1;
        const float* preb = g_pre + ((size_t)(sc*2 + b)*KKEY << 6);
        const uint2* wps = wpk + sc*2560;
        const float* wx = wxyz + sc*192;
        const float bias0a = b0s[sc*64 + lane],  bias0b = b0s[sc*64 + lane + 32];
        const float wxa0 = wx[lane],    wxa1 = wx[64+lane],  wxa2 = wx[128+lane];
        const float wxb0 = wx[lane+32], wxb1 = wx[96+lane],  wxb2 = wx[160+lane];

        float cm0[8], cm1[8];
        #pragma unroll
        for (int nt = 0; nt < 8; nt++) { cm0[nt] = -3.4e38f; cm1[nt] = -3.4e38f; }

        for (int pass = 0; pass < NPASS; pass++) {
            const float4* relb = sc ? (relw + 16 + pass*16) : relw;
            // ---- layer 0: 16 samples, row-paired (s, s+8), STS.128 ----
            #pragma unroll
            for (int sb = 0; sb < 8; sb += 2) {
                float4 rv[4];
                float2 pr[4];
                #pragma unroll
                for (int q = 0; q < 4; q++) {
                    int si = sb + (q & 1) + ((q >> 1) << 3);
                    rv[q] = relb[si];
                    int k = __float_as_int(rv[q].w);
                    pr[q] = *(const float2*)(preb + ((size_t)k << 6) + (lane << 1));
                }
                unsigned va[4], vb[4];
                #pragma unroll
                for (int q = 0; q < 4; q++) {
                    float a = pr[q].x + bias0a;
                    a = fmaf(rv[q].x, wxa0, a);
                    a = fmaf(rv[q].y, wxa1, a);
                    a = fmaf(rv[q].z, wxa2, a);
                    float bv = pr[q].y + bias0b;
                    bv = fmaf(rv[q].x, wxb0, bv);
                    bv = fmaf(rv[q].y, wxb1, bv);
                    bv = fmaf(rv[q].z, wxb2, bv);
                    va[q] = f2tf32(fmaxf(a, 0.f));
                    vb[q] = f2tf32(fmaxf(bv, 0.f));
                }
                *(uint4*)(hw + (sb  )*HW_PITCH + colu) =
                    make_uint4(va[0], va[2], vb[0], vb[2]);
                *(uint4*)(hw + (sb+1)*HW_PITCH + colu) =
                    make_uint4(va[1], va[3], vb[1], vb[3]);
            }
            __syncwarp();

            // ---- layer 1 MMA ----
            float acc[8][4];
            #pragma unroll
            for (int nt = 0; nt < 8; nt++)
                acc[nt][0] = acc[nt][1] = acc[nt][2] = acc[nt][3] = 0.f;
            #pragma unroll
            for (int kt = 0; kt < 8; kt++) {
                uint4 af = *(const uint4*)(hw + gid*HW_PITCH + kt*16 + tig*4);
                const uint2* wk = wps + kt*320 + lane*10;
                #pragma unroll
                for (int ntp = 0; ntp < 4; ntp++) {
                    uint4 bp = *(const uint4*)(wk + ntp*2);
                    mma_tf32(acc[2*ntp],   af.x, af.y, af.z, af.w, bp.x, bp.y);
                    mma_tf32(acc[2*ntp+1], af.x, af.y, af.z, af.w, bp.z, bp.w);
                }
            }
            #pragma unroll
            for (int nt = 0; nt < 8; nt++) {
                cm0[nt] = fmaxf(cm0[nt], fmaxf(acc[nt][0], acc[nt][2]));
                cm1[nt] = fmaxf(cm1[nt], fmaxf(acc[nt][1], acc[nt][3]));
            }
            __syncwarp();
        }

        #pragma unroll
        for (int off = 4; off <= 16; off <<= 1) {
            #pragma unroll
            for (int nt = 0; nt < 8; nt++) {
                cm0[nt] = fmaxf(cm0[nt], __shfl_xor_sync(0xffffffffu, cm0[nt], off));
                cm1[nt] = fmaxf(cm1[nt], __shfl_xor_sync(0xffffffffu, cm1[nt], off));
            }
        }
        // stage into smem (coalesced block store later)
        if (gid == 0) {
            #pragma unroll
            for (int nt = 0; nt < 8; nt++) {
                int o0 = nt*8 + tig*2;
                float v0 = fmaxf(cm0[nt] + b1s[sc*64 + o0],     0.f);
                float v1 = fmaxf(cm1[nt] + b1s[sc*64 + o0 + 1], 0.f);
                outs[(sc*64 + o0)*12 + w]     = v0;
                outs[(sc*64 + o0 + 1)*12 + w] = v1;
            }
        }
    }

    // ---- cooperative coalesced write: 128 segments x 12 floats ----
    __syncthreads();
    {
        const int pblock = blockIdx.x*12;
        const int bb = pblock / NPTS;
        const int rpb = pblock % NPTS;
        const int nb = rpb / M_GRID, mm0 = rpb % M_GRID;   // mm0 multiple of 12
        const size_t rowb = (size_t)(bb*NPROP + nb)*QDIM;
        const int seg = threadIdx.x / 3, part = threadIdx.x % 3;
        float4 v = *(const float4*)(outs + seg*12 + part*4);
        *(float4*)(g_pooled + rowb + (size_t)seg*M_GRID + mm0 + part*4) = v;
    }
}

// ---------------- kernel D: K-split GEMM via tf32 MMA (R10, validated) ------
#define XDP 18
__global__ void __launch_bounds__(384) kD(const float* __restrict__ w0) {
    __shared__ unsigned xs[2][96*XDP];
    __shared__ unsigned ws[2][64*XDP];
    const int tid = threadIdx.x;
    const int w = tid >> 5, lane = tid & 31;
    const int gid = lane >> 2, tig = lane & 3;
    const int rg = w % 6, cg = w / 6;
    const int colbase = blockIdx.x * 64;
    const int kg0 = blockIdx.y * KCHUNK;

    const int frow = tid >> 2;
    const int fq   = (tid & 3) << 2;
    const int slotb = ((fq & 4) << 1) + (fq >> 3);

    const float* xg = g_pooled + (size_t)frow*QDIM + kg0 + fq;
    const float* wg = w0 + (size_t)(colbase + (tid >> 2))*QDIM + kg0 + ((tid & 3) << 2);

    float4 xv = *(const float4*)xg;
    float4 wv = make_float4(0.f,0.f,0.f,0.f);
    if (tid < 256) wv = *(const float4*)wg;

    float acc[4][4] = {};
    const int NT = KCHUNK / 16;
    for (int t = 0; t < NT; t++) {
        unsigned* xsc = xs[t & 1];
        unsigned* wsc = ws[t & 1];
        {
            unsigned* d = xsc + frow*XDP + slotb;
            d[0] = f2tf32(xv.x); d[2] = f2tf32(xv.y);
            d[4] = f2tf32(xv.z); d[6] = f2tf32(xv.w);
        }
        if (tid < 256) {
            unsigned* d = wsc + (tid >> 2)*XDP + slotb;
            d[0] = f2tf32(wv.x); d[2] = f2tf32(wv.y);
            d[4] = f2tf32(wv.z); d[6] = f2tf32(wv.w);
        }
        __syncthreads();
        if (t + 1 < NT) {
            xv = *(const float4*)(xg + (t + 1)*16);
            if (tid < 256) wv = *(const float4*)(wg + (t + 1)*16);
        }
        #pragma unroll
        for (int kt = 0; kt < 2; kt++) {
            uint2 alo = *(const uint2*)(xsc + (rg*16 + gid    )*XDP + kt*8 + tig*2);
            uint2 ahi = *(const uint2*)(xsc + (rg*16 + gid + 8)*XDP + kt*8 + tig*2);
            #pragma unroll
            for (int nt = 0; nt < 4; nt++) {
                uint2 bb = *(const uint2*)(wsc + (cg*32 + nt*8 + gid)*XDP + kt*8 + tig*2);
                mma_tf32(acc[nt], alo.x, ahi.x, alo.y, ahi.y, bb.x, bb.y);
            }
        }
        __syncthreads();
    }
    #pragma unroll
    for (int nt = 0; nt < 4; nt++) {
        int col = colbase + cg*32 + nt*8 + tig*2;
        int row = rg*16 + gid;
        float* pp = g_partial + ((size_t)blockIdx.y*96 + row)*256 + col;
        *(float2*)pp             = make_float2(acc[nt][0], acc[nt][1]);
        *(float2*)(pp + 8*256)   = make_float2(acc[nt][2], acc[nt][3]);
    }
}

// ---------------- kernel E: reduce + relu + 256x256 GEMM + relu ------------
__global__ void __launch_bounds__(256) kE(const float* __restrict__ rb0,
                                          const float* __restrict__ rw1,
                                          const float* __restrict__ rb1,
                                          float* __restrict__ out) {
    __shared__ float h2s[256];
    __shared__ float w1s[256*33];
    const int row = blockIdx.x;
    const int o = threadIdx.x;
    float s = rb0[o];
    #pragma unroll 4
    for (int ks = 0; ks < KSPLIT; ks++)
        s += g_partial[((size_t)ks*96 + row)*256 + o];
    h2s[o] = fmaxf(s, 0.f);
    __syncthreads();

    float acc = rb1[o];
    for (int jt = 0; jt < 256; jt += 32) {
        for (int i = threadIdx.x; i < 8192; i += 256) {
            int oo = i >> 5, jj = i & 31;
            w1s[oo*33 + jj] = rw1[(size_t)oo*256 + jt + jj];
        }
        __syncthreads();
        #pragma unroll
        for (int jj = 0; jj < 32; jj++)
            acc = fmaf(h2s[jt + jj], w1s[o*33 + jj], acc);
        __syncthreads();
    }
    out[(size_t)row*256 + o] = fmaxf(acc, 0.f);
}

// ---------------- launch ----------------
extern "C" void kernel_launch(void* const* d_in, const int* in_sizes, int n_in,
                              void* d_out, int out_size) {
    const float* proposals = (const float*)d_in[0];
    const float* kxyz      = (const float*)d_in[1];
    const float* kfeat     = (const float*)d_in[2];
    const float* gnoise    = (const float*)d_in[3];
    const float* w00 = (const float*)d_in[4];
    const float* b00 = (const float*)d_in[5];
    const float* w01 = (const float*)d_in[6];
    const float* b01 = (const float*)d_in[7];
    const float* w10 = (const float*)d_in[8];
    const float* b10 = (const float*)d_in[9];
    const float* w11 = (const float*)d_in[10];
    const float* b11 = (const float*)d_in[11];
    const float* rw0 = (const float*)d_in[12];
    const float* rb0 = (const float*)d_in[13];
    const float* rw1 = (const float*)d_in[14];
    const float* rb1 = (const float*)d_in[15];
    float* out = (float*)d_out;

    cudaFuncSetAttribute(kC2, cudaFuncAttributeMaxDynamicSharedMemorySize,
                         KC2_SMEM_WORDS * 4);

    kB<<<dim3(KKEY/32, 4), 256>>>(kfeat, w00, w10);
    kQ<<<NTOT/16, 512>>>(proposals, gnoise, kxyz);
    kC2<<<NTOT/12, 384, KC2_SMEM_WORDS * 4>>>(w00, b00, w01, b01,
                                              w10, b10, w11, b11);
    kD<<<dim3(4, KSPLIT), 384>>>(rw0);
    kE<<<96, 256>>>(rb0, rw1, rb1, out);
}

// round 13
// speedup vs baseline: 1.0028x; 1.0028x over previous
#include <cuda_runtime.h>
#include <math.h>

#define KKEY   2048
#define CFEAT  128
#define M_GRID 216
#define NPROP  48
#define NPTS   (NPROP*M_GRID)      // 10368 per batch
#define NTOT   (2*NPTS)            // 20736
#define QDIM   (128*M_GRID)        // 27648
#define KSPLIT 108
#define KCHUNK 256

typedef unsigned long long ull;

__device__ __forceinline__ ull pack2(float lo, float hi) {
    ull r; asm("mov.b64 %0, {%1, %2};" : "=l"(r) : "f"(lo), "f"(hi)); return r;
}
__device__ __forceinline__ ull ffma2(ull a, ull b, ull c) {
    ull d; asm("fma.rn.f32x2 %0, %1, %2, %3;" : "=l"(d) : "l"(a), "l"(b), "l"(c)); return d;
}
__device__ __forceinline__ float2 unpack2(ull v) {
    float2 f; asm("mov.b64 {%0, %1}, %2;" : "=f"(f.x), "=f"(f.y) : "l"(v)); return f;
}
__device__ __forceinline__ unsigned f2tf32(float v) {
    unsigned u; asm("cvt.rna.tf32.f32 %0, %1;" : "=r"(u) : "f"(v)); return u;
}
__device__ __forceinline__ void mma_tf32(float d[4], const unsigned a0, const unsigned a1,
                                         const unsigned a2, const unsigned a3,
                                         const unsigned b0, const unsigned b1) {
    asm("mma.sync.aligned.m16n8k8.row.col.f32.tf32.tf32.f32 "
        "{%0,%1,%2,%3}, {%4,%5,%6,%7}, {%8,%9}, {%0,%1,%2,%3};"
        : "+f"(d[0]), "+f"(d[1]), "+f"(d[2]), "+f"(d[3])
        : "r"(a0), "r"(a1), "r"(a2), "r"(a3), "r"(b0), "r"(b1));
}

// ---------------- scratch ----------------
__device__ float  g_pre[2*2*KKEY*64];        // [scale][b][k][interleaved o]
__device__ float4 g_rel1[NTOT*32];           // {rx,ry,rz, bitcast k}
__device__ float4 g_rel0[NTOT*16];
__device__ float  g_pooled[2*NPROP*QDIM];    // 96 x 27648, q = co*216+mm
__device__ float  g_partial[KSPLIT*96*256];

// ---------------- kernel B: pre[k][o] = W0[:,3:] . feats[:,k] ----------------
__global__ void __launch_bounds__(256) kB(const float* __restrict__ feats,
                                          const float* __restrict__ w0,
                                          const float* __restrict__ w1) {
    __shared__ float Ws[CFEAT*64];
    __shared__ float fs[CFEAT*32];
    int sb = blockIdx.y; int sc = sb >> 1, b = sb & 1;
    const float* W = sc ? w1 : w0;
    for (int i = threadIdx.x; i < CFEAT*64; i += 256) {
        int c = i >> 6, o = i & 63;
        Ws[i] = W[o*131 + 3 + c];
    }
    int kbase = blockIdx.x * 32;
    const float* fb = feats + (size_t)b*CFEAT*KKEY + kbase;
    for (int i = threadIdx.x; i < CFEAT*8; i += 256) {
        int c = i >> 3, q = i & 7;
        *(float4*)(fs + c*32 + q*4) = *(const float4*)(fb + (size_t)c*KKEY + q*4);
    }
    __syncthreads();

    int o  = threadIdx.x & 63;
    int kk = threadIdx.x >> 6;
    ull acc0 = 0, acc1 = 0, acc2 = 0, acc3 = 0;
    #pragma unroll 4
    for (int c = 0; c < CFEAT; c++) {
        float w = Ws[c*64 + o];
        ull wd = pack2(w, w);
        const ull* f = (const ull*)(fs + c*32 + kk*8);
        acc0 = ffma2(wd, f[0], acc0);
        acc1 = ffma2(wd, f[1], acc1);
        acc2 = ffma2(wd, f[2], acc2);
        acc3 = ffma2(wd, f[3], acc3);
    }
    size_t base = ((size_t)(sc*2 + b)*KKEY + kbase + kk*8) << 6;
    int oi = ((o & 31) << 1) + (o >> 5);
    float2 u;
    u = unpack2(acc0); g_pre[base + oi] = u.x; g_pre[base + 64 + oi] = u.y;
    u = unpack2(acc1); g_pre[base + 128 + oi] = u.x; g_pre[base + 192 + oi] = u.y;
    u = unpack2(acc2); g_pre[base + 256 + oi] = u.x; g_pre[base + 320 + oi] = u.y;
    u = unpack2(acc3); g_pre[base + 384 + oi] = u.x; g_pre[base + 448 + oi] = u.y;
}

// ---------------- kernel Q: grid transform + ball query -> rel coords -------
__global__ void __launch_bounds__(512) kQ(const float* __restrict__ prop,
                                          const float* __restrict__ gnoise,
                                          const float* __restrict__ kxyzg) {
    __shared__ float4 kp4[KKEY];               // {x,y,z,|k|^2}, 32KB
    __shared__ int idx1s[16][32], idx0s[16][16];

    const int b = blockIdx.x / 648;
    const float* kb = kxyzg + (size_t)b*KKEY*3;
    for (int i = threadIdx.x; i < KKEY; i += 512) {
        float x = kb[i*3], y = kb[i*3+1], z = kb[i*3+2];
        kp4[i] = make_float4(x, y, z, fmaf(x,x, fmaf(y,y, z*z)));
    }
    __syncthreads();

    const int w = threadIdx.x >> 5, lane = threadIdx.x & 31;
    const int p = blockIdx.x*16 + w;
    const int rp = p % NPTS;
    const int n = rp / M_GRID, mmq = rp % M_GRID;

    // fused kA: xyz of this point (same expressions as original kA)
    const float* p7 = prop + (size_t)(b*NPROP + n)*7;
    const float* gg = gnoise + ((size_t)(b*NPROP + n)*M_GRID + mmq)*3;
    float gx = gg[0]*p7[3], gy = gg[1]*p7[4], gz = gg[2]*p7[5];
    float cth = cosf(p7[6]), sth = sinf(p7[6]);
    const float px = cth*gx - sth*gy + p7[0];
    const float py = sth*gx + cth*gy + p7[1];
    const float pz = gz + p7[2];
    const float pn = fmaf(px,px, fmaf(py,py, pz*pz));

    const float R0 = 0.8f*0.8f, R1 = 1.6f*1.6f;
    int* l1 = idx1s[w];
    int* l0 = idx0s[w];
    int c0 = 0, c1 = 0;
    const unsigned lt = (1u << lane) - 1u;
    for (int base = 0; base < KKEY; base += 32) {
        int k = base + lane;
        float4 kk = kp4[k];
        float dot = fmaf(px,kk.x, fmaf(py,kk.y, pz*kk.z));
        float d2  = fmaf(-2.f, dot, pn + kk.w);
        bool v1 = d2 < R1, v0 = d2 < R0;
        unsigned m1 = __ballot_sync(0xffffffffu, v1);
        unsigned m0 = __ballot_sync(0xffffffffu, v0);
        if (c1 < 32 && m1) {
            if (v1) { int rk = c1 + __popc(m1 & lt); if (rk < 32) l1[rk] = k; }
            c1 = min(32, c1 + __popc(m1));
        }
        if (c0 < 16 && m0) {
            if (v0) { int rk = c0 + __popc(m0 & lt); if (rk < 16) l0[rk] = k; }
            c0 = min(16, c0 + __popc(m0));
        }
        if (c0 >= 16 && c1 >= 32) break;
    }
    __syncwarp();
    if (c1 == 0) { if (lane == 0) l1[0] = 0; c1 = 1; }
    if (c0 == 0) { if (lane == 0) l0[0] = 0; c0 = 1; }
    __syncwarp();
    {
        int f1 = l1[0], f0 = l0[0];
        if (lane >= c1) l1[lane] = f1;
        if (lane < 16 && lane >= c0) l0[lane] = f0;
    }
    __syncwarp();

    {
        int k = l1[lane];
        float4 kk = kp4[k];
        g_rel1[(size_t)p*32 + lane] =
            make_float4(kk.x-px, kk.y-py, kk.z-pz, __int_as_float(k));
        if (lane < 16) {
            int k0 = l0[lane];
            float4 k4 = kp4[k0];
            g_rel0[(size_t)p*16 + lane] =
                make_float4(k4.x-px, k4.y-py, k4.z-pz, __int_as_float(k0));
        }
    }
}

// ---------------- kernel C2: 1 pt/warp, 128-bit smem, direct epilogue -------
// (R11 kC2, validated at 107us; epilogue = direct scattered stores)
#define KC2_SMEM_WORDS 27008
#define OFF2_WXYZ 10240
#define OFF2_B0   10624
#define OFF2_B1   10752
#define OFF2_HW   10880
#define OFF2_REL  24704
#define HW_PITCH  144

__global__ void __launch_bounds__(384, 2) kC2(
    const float* __restrict__ w00, const float* __restrict__ b00,
    const float* __restrict__ w01, const float* __restrict__ b01,
    const float* __restrict__ w10, const float* __restrict__ b10,
    const float* __restrict__ w11, const float* __restrict__ b11)
{
    extern __shared__ float sm[];
    uint2*    wpk  = (uint2*)sm;               // [sc][kt][lane][nt pad10]
    float*    wxyz = sm + OFF2_WXYZ;
    float*    b0s  = sm + OFF2_B0;
    float*    b1s  = sm + OFF2_B1;
    unsigned* hwg  = (unsigned*)(sm + OFF2_HW);
    float4*   relg = (float4*)(sm + OFF2_REL);

    for (int i = threadIdx.x; i < 2*8*32*8; i += 384) {
        int nt = i & 7, lane2 = (i >> 3) & 31, kt = (i >> 8) & 7, sc = i >> 11;
        int gid2 = lane2 >> 2, tig2 = lane2 & 3;
        const float* W1 = sc ? w11 : w01;
        int o = nt*8 + gid2;
        int j = kt*4 + tig2;
        wpk[sc*2560 + kt*320 + lane2*10 + nt] =
            make_uint2(f2tf32(W1[o*64 + j]), f2tf32(W1[o*64 + j + 32]));
    }
    for (int i = threadIdx.x; i < 2*3*64; i += 384) {
        int sc = i / 192, t = i % 192, d = t / 64, o = t % 64;
        wxyz[i] = (sc ? w10 : w00)[o*131 + d];
    }
    if (threadIdx.x < 256) {
        int sc = (threadIdx.x >> 6) & 1, o = threadIdx.x & 63;
        if (threadIdx.x < 128) b0s[threadIdx.x] = (sc ? b10 : b00)[o];
        else                   b1s[threadIdx.x - 128] = (sc ? b11 : b01)[o];
    }
    __syncthreads();

    const int w = threadIdx.x >> 5, lane = threadIdx.x & 31;
    const int gid = lane >> 2, tig = lane & 3;
    const int p  = blockIdx.x*12 + w;
    const int b  = p / NPTS;
    const int rp = p % NPTS;
    const int n  = rp / M_GRID, mm = rp % M_GRID;

    unsigned* hw = hwg + w*8*HW_PITCH;
    float4*   relw = relg + w*48;
    const int colu = gid*16 + tig*4;

    relw[16 + lane] = g_rel1[(size_t)p*32 + lane];
    if (lane < 16) relw[lane] = g_rel0[(size_t)p*16 + lane];
    __syncwarp();

    #pragma unroll
    for (int sc = 0; sc < 2; sc++) {
        const int NPASS = sc ? 2 : 1;
        const float* preb = g_pre + ((size_t)(sc*2 + b)*KKEY << 6);
        const uint2* wps = wpk + sc*2560;
        const float* wx = wxyz + sc*192;
        const float bias0a = b0s[sc*64 + lane],  bias0b = b0s[sc*64 + lane + 32];
        const float wxa0 = wx[lane],    wxa1 = wx[64+lane],  wxa2 = wx[128+lane];
        const float wxb0 = wx[lane+32], wxb1 = wx[96+lane],  wxb2 = wx[160+lane];

        float cm0[8], cm1[8];
        #pragma unroll
        for (int nt = 0; nt < 8; nt++) { cm0[nt] = -3.4e38f; cm1[nt] = -3.4e38f; }

        for (int pass = 0; pass < NPASS; pass++) {
            const float4* relb = sc ? (relw + 16 + pass*16) : relw;
            // ---- layer 0: 16 samples, row-paired (s, s+8), STS.128 ----
            #pragma unroll
            for (int sb = 0; sb < 8; sb += 2) {
                float4 rv[4];
                float2 pr[4];
                #pragma unroll
                for (int q = 0; q < 4; q++) {
                    int si = sb + (q & 1) + ((q >> 1) << 3);
                    rv[q] = relb[si];
                    int k = __float_as_int(rv[q].w);
                    pr[q] = *(const float2*)(preb + ((size_t)k << 6) + (lane << 1));
                }
                unsigned va[4], vb[4];
                #pragma unroll
                for (int q = 0; q < 4; q++) {
                    float a = pr[q].x + bias0a;
                    a = fmaf(rv[q].x, wxa0, a);
                    a = fmaf(rv[q].y, wxa1, a);
                    a = fmaf(rv[q].z, wxa2, a);
                    float bv = pr[q].y + bias0b;
                    bv = fmaf(rv[q].x, wxb0, bv);
                    bv = fmaf(rv[q].y, wxb1, bv);
                    bv = fmaf(rv[q].z, wxb2, bv);
                    va[q] = f2tf32(fmaxf(a, 0.f));
                    vb[q] = f2tf32(fmaxf(bv, 0.f));
                }
                *(uint4*)(hw + (sb  )*HW_PITCH + colu) =
                    make_uint4(va[0], va[2], vb[0], vb[2]);
                *(uint4*)(hw + (sb+1)*HW_PITCH + colu) =
                    make_uint4(va[1], va[3], vb[1], vb[3]);
            }
            __syncwarp();

            // ---- layer 1 MMA: a = 1 LDS.128, b = 4 LDS.128 per kt ----
            float acc[8][4];
            #pragma unroll
            for (int nt = 0; nt < 8; nt++)
                acc[nt][0] = acc[nt][1] = acc[nt][2] = acc[nt][3] = 0.f;
            #pragma unroll
            for (int kt = 0; kt < 8; kt++) {
                uint4 af = *(const uint4*)(hw + gid*HW_PITCH + kt*16 + tig*4);
                const uint2* wk = wps + kt*320 + lane*10;
                #pragma unroll
                for (int ntp = 0; ntp < 4; ntp++) {
                    uint4 bp = *(const uint4*)(wk + ntp*2);
                    mma_tf32(acc[2*ntp],   af.x, af.y, af.z, af.w, bp.x, bp.y);
                    mma_tf32(acc[2*ntp+1], af.x, af.y, af.z, af.w, bp.z, bp.w);
                }
            }
            #pragma unroll
            for (int nt = 0; nt < 8; nt++) {
                cm0[nt] = fmaxf(cm0[nt], fmaxf(acc[nt][0], acc[nt][2]));
                cm1[nt] = fmaxf(cm1[nt], fmaxf(acc[nt][1], acc[nt][3]));
            }
            __syncwarp();
        }

        // reduce across row-groups (lane bits 2..4)
        #pragma unroll
        for (int off = 4; off <= 16; off <<= 1) {
            #pragma unroll
            for (int nt = 0; nt < 8; nt++) {
                cm0[nt] = fmaxf(cm0[nt], __shfl_xor_sync(0xffffffffu, cm0[nt], off));
                cm1[nt] = fmaxf(cm1[nt], __shfl_xor_sync(0xffffffffu, cm1[nt], off));
            }
        }
        size_t rowb = (size_t)(b*NPROP + n)*QDIM + (size_t)sc*64*M_GRID + mm;
        if (gid == 0) {
            #pragma unroll
            for (int nt = 0; nt < 8; nt++) {
                int o0 = nt*8 + tig*2;
                float v0 = fmaxf(cm0[nt] + b1s[sc*64 + o0],     0.f);
                float v1 = fmaxf(cm1[nt] + b1s[sc*64 + o0 + 1], 0.f);
                g_pooled[rowb + (size_t)o0*M_GRID]     = v0;
                g_pooled[rowb + (size_t)(o0+1)*M_GRID] = v1;
            }
        }
    }
}

// ---------------- kernel D: K-split tf32 MMA, 32-k tiles (half the syncs) ---
// Per 32-k tile: two 16-k subtiles at slot bases 0 and 20 within pitch-40 rows.
// a/b frag LDS.64 conflict-free: banks (40r + 2t) mod 32 distinct per half-warp.
#define KD_KT 32
#define XDP 40
__global__ void __launch_bounds__(384) kD(const float* __restrict__ w0) {
    __shared__ unsigned xs[96*XDP];    // 15360 words
    __shared__ unsigned ws[64*XDP];    // 10240 words
    const int tid = threadIdx.x;
    const int w = tid >> 5, lane = tid & 31;
    const int gid = lane >> 2, tig = lane & 3;
    const int rg = w % 6, cg = w / 6;
    const int colbase = blockIdx.x * 64;
    const int kg0 = blockIdx.y * KCHUNK;

    const int frow = tid >> 2;
    const int fq   = (tid & 3) << 2;
    const int slotb = ((fq & 4) << 1) + (fq >> 3);

    const float* xg = g_pooled + (size_t)frow*QDIM + kg0 + fq;
    const float* wg = w0 + (size_t)(colbase + (tid >> 2))*QDIM + kg0 + ((tid & 3) << 2);

    float4 xv0 = *(const float4*)xg;
    float4 xv1 = *(const float4*)(xg + 16);
    float4 wv0 = make_float4(0.f,0.f,0.f,0.f), wv1 = wv0;
    if (tid < 256) { wv0 = *(const float4*)wg; wv1 = *(const float4*)(wg + 16); }

    float acc[4][4] = {};
    const int NT = KCHUNK / KD_KT;              // 8
    for (int t = 0; t < NT; t++) {
        __syncthreads();                        // prior compute done
        {
            unsigned* d = xs + frow*XDP + slotb;
            d[0]  = f2tf32(xv0.x); d[2]  = f2tf32(xv0.y);
            d[4]  = f2tf32(xv0.z); d[6]  = f2tf32(xv0.w);
            d[20] = f2tf32(xv1.x); d[22] = f2tf32(xv1.y);
            d[24] = f2tf32(xv1.z); d[26] = f2tf32(xv1.w);
        }
        if (tid < 256) {
            unsigned* d = ws + (tid >> 2)*XDP + slotb;
            d[0]  = f2tf32(wv0.x); d[2]  = f2tf32(wv0.y);
            d[4]  = f2tf32(wv0.z); d[6]  = f2tf32(wv0.w);
            d[20] = f2tf32(wv1.x); d[22] = f2tf32(wv1.y);
            d[24] = f2tf32(wv1.z); d[26] = f2tf32(wv1.w);
        }
        __syncthreads();
        if (t + 1 < NT) {
            int dlt = (t + 1) * KD_KT;
            xv0 = *(const float4*)(xg + dlt);
            xv1 = *(const float4*)(xg + dlt + 16);
            if (tid < 256) {
                wv0 = *(const float4*)(wg + dlt);
                wv1 = *(const float4*)(wg + dlt + 16);
            }
        }
        #pragma unroll
        for (int kt = 0; kt < 4; kt++) {
            int off = (kt >> 1)*20 + (kt & 1)*8 + tig*2;
            uint2 alo = *(const uint2*)(xs + (rg*16 + gid    )*XDP + off);
            uint2 ahi = *(const uint2*)(xs + (rg*16 + gid + 8)*XDP + off);
            #pragma unroll
            for (int nt = 0; nt < 4; nt++) {
                uint2 bb = *(const uint2*)(ws + (cg*32 + nt*8 + gid)*XDP + off);
                mma_tf32(acc[nt], alo.x, ahi.x, alo.y, ahi.y, bb.x, bb.y);
            }
        }
    }
    #pragma unroll
    for (int nt = 0; nt < 4; nt++) {
        int col = colbase + cg*32 + nt*8 + tig*2;
        int row = rg*16 + gid;
        float* pp = g_partial + ((size_t)blockIdx.y*96 + row)*256 + col;
        *(float2*)pp             = make_float2(acc[nt][0], acc[nt][1]);
        *(float2*)(pp + 8*256)   = make_float2(acc[nt][2], acc[nt][3]);
    }
}

// ---------------- kernel E: reduce + relu + 256x256 GEMM + relu ------------
__global__ void __launch_bounds__(256) kE(const float* __restrict__ rb0,
                                          const float* __restrict__ rw1,
                                          const float* __restrict__ rb1,
                                          float* __restrict__ out) {
    __shared__ float h2s[256];
    __shared__ float w1s[256*33];
    const int row = blockIdx.x;
    const int o = threadIdx.x;
    float s = rb0[o];
    #pragma unroll 4
    for (int ks = 0; ks < KSPLIT; ks++)
        s += g_partial[((size_t)ks*96 + row)*256 + o];
    h2s[o] = fmaxf(s, 0.f);
    __syncthreads();

    float acc = rb1[o];
    for (int jt = 0; jt < 256; jt += 32) {
        for (int i = threadIdx.x; i < 8192; i += 256) {
            int oo = i >> 5, jj = i & 31;
            w1s[oo*33 + jj] = rw1[(size_t)oo*256 + jt + jj];
        }
        __syncthreads();
        #pragma unroll
        for (int jj = 0; jj < 32; jj++)
            acc = fmaf(h2s[jt + jj], w1s[o*33 + jj], acc);
        __syncthreads();
    }
    out[(size_t)row*256 + o] = fmaxf(acc, 0.f);
}

// ---------------- launch ----------------
extern "C" void kernel_launch(void* const* d_in, const int* in_sizes, int n_in,
                              void* d_out, int out_size) {
    const float* proposals = (const float*)d_in[0];
    const float* kxyz      = (const float*)d_in[1];
    const float* kfeat     = (const float*)d_in[2];
    const float* gnoise    = (const float*)d_in[3];
    const float* w00 = (const float*)d_in[4];
    const float* b00 = (const float*)d_in[5];
    const float* w01 = (const float*)d_in[6];
    const float* b01 = (const float*)d_in[7];
    const float* w10 = (const float*)d_in[8];
    const float* b10 = (const float*)d_in[9];
    const float* w11 = (const float*)d_in[10];
    const float* b11 = (const float*)d_in[11];
    const float* rw0 = (const float*)d_in[12];
    const float* rb0 = (const float*)d_in[13];
    const float* rw1 = (const float*)d_in[14];
    const float* rb1 = (const float*)d_in[15];
    float* out = (float*)d_out;

    cudaFuncSetAttribute(kC2, cudaFuncAttributeMaxDynamicSharedMemorySize,
                         KC2_SMEM_WORDS * 4);

    kB<<<dim3(KKEY/32, 4), 256>>>(kfeat, w00, w10);
    kQ<<<NTOT/16, 512>>>(proposals, gnoise, kxyz);
    kC2<<<NTOT/12, 384, KC2_SMEM_WORDS * 4>>>(w00, b00, w01, b01,
                                              w10, b10, w11, b11);
    kD<<<dim3(4, KSPLIT), 384>>>(rw0);
    kE<<<96, 256>>>(rb0, rw1, rb1, out);
}

// round 14
// speedup vs baseline: 1.0331x; 1.0302x over previous
#include <cuda_runtime.h>
#include <math.h>

#define KKEY   2048
#define CFEAT  128
#define M_GRID 216
#define NPROP  48
#define NPTS   (NPROP*M_GRID)      // 10368 per batch
#define NTOT   (2*NPTS)            // 20736
#define QDIM   (128*M_GRID)        // 27648
#define KSPLIT 108
#define KCHUNK 256

typedef unsigned long long ull;

__device__ __forceinline__ ull pack2(float lo, float hi) {
    ull r; asm("mov.b64 %0, {%1, %2};" : "=l"(r) : "f"(lo), "f"(hi)); return r;
}
__device__ __forceinline__ ull ffma2(ull a, ull b, ull c) {
    ull d; asm("fma.rn.f32x2 %0, %1, %2, %3;" : "=l"(d) : "l"(a), "l"(b), "l"(c)); return d;
}
__device__ __forceinline__ float2 unpack2(ull v) {
    float2 f; asm("mov.b64 {%0, %1}, %2;" : "=f"(f.x), "=f"(f.y) : "l"(v)); return f;
}
__device__ __forceinline__ unsigned f2tf32(float v) {
    unsigned u; asm("cvt.rna.tf32.f32 %0, %1;" : "=r"(u) : "f"(v)); return u;
}
__device__ __forceinline__ void mma_tf32(float d[4], const unsigned a0, const unsigned a1,
                                         const unsigned a2, const unsigned a3,
                                         const unsigned b0, const unsigned b1) {
    asm("mma.sync.aligned.m16n8k8.row.col.f32.tf32.tf32.f32 "
        "{%0,%1,%2,%3}, {%4,%5,%6,%7}, {%8,%9}, {%0,%1,%2,%3};"
        : "+f"(d[0]), "+f"(d[1]), "+f"(d[2]), "+f"(d[3])
        : "r"(a0), "r"(a1), "r"(a2), "r"(a3), "r"(b0), "r"(b1));
}

// ---------------- scratch ----------------
__device__ float  g_new_xyz[NTOT*3];
__device__ float  g_pre[2*2*KKEY*64];        // [scale][b][k][interleaved o]
__device__ float4 g_rel1[NTOT*32];           // {rx,ry,rz, bitcast k}
__device__ float4 g_rel0[NTOT*16];
__device__ float  g_pooled[2*NPROP*QDIM];    // 96 x 27648, q = co*216+mm
__device__ float  g_partial[KSPLIT*96*256];

// ---------------- kernel A: grid transform -> new_xyz ----------------
__global__ void __launch_bounds__(256) kA(const float* __restrict__ prop,
                                          const float* __restrict__ gnoise) {
    int t = blockIdx.x*256 + threadIdx.x;
    if (t >= NTOT) return;
    int b = t / NPTS, r = t % NPTS;
    int n = r / M_GRID, mm = r % M_GRID;
    const float* p = prop + (size_t)(b*NPROP + n)*7;
    const float* g = gnoise + ((size_t)(b*NPROP + n)*M_GRID + mm)*3;
    float gx = g[0]*p[3], gy = g[1]*p[4], gz = g[2]*p[5];
    float c = cosf(p[6]), s = sinf(p[6]);
    float* o = g_new_xyz + (size_t)t*3;
    o[0] = c*gx - s*gy + p[0];
    o[1] = s*gx + c*gy + p[1];
    o[2] = gz + p[2];
}

// ---------------- kernel B: pre[k][o] = W0[:,3:] . feats[:,k] ----------------
__global__ void __launch_bounds__(256) kB(const float* __restrict__ feats,
                                          const float* __restrict__ w0,
                                          const float* __restrict__ w1) {
    __shared__ float Ws[CFEAT*64];
    __shared__ float fs[CFEAT*32];
    int sb = blockIdx.y; int sc = sb >> 1, b = sb & 1;
    const float* W = sc ? w1 : w0;
    for (int i = threadIdx.x; i < CFEAT*64; i += 256) {
        int c = i >> 6, o = i & 63;
        Ws[i] = W[o*131 + 3 + c];
    }
    int kbase = blockIdx.x * 32;
    const float* fb = feats + (size_t)b*CFEAT*KKEY + kbase;
    for (int i = threadIdx.x; i < CFEAT*8; i += 256) {
        int c = i >> 3, q = i & 7;
        *(float4*)(fs + c*32 + q*4) = *(const float4*)(fb + (size_t)c*KKEY + q*4);
    }
    __syncthreads();

    int o  = threadIdx.x & 63;
    int kk = threadIdx.x >> 6;
    ull acc0 = 0, acc1 = 0, acc2 = 0, acc3 = 0;
    #pragma unroll 4
    for (int c = 0; c < CFEAT; c++) {
        float w = Ws[c*64 + o];
        ull wd = pack2(w, w);
        const ull* f = (const ull*)(fs + c*32 + kk*8);
        acc0 = ffma2(wd, f[0], acc0);
        acc1 = ffma2(wd, f[1], acc1);
        acc2 = ffma2(wd, f[2], acc2);
        acc3 = ffma2(wd, f[3], acc3);
    }
    size_t base = ((size_t)(sc*2 + b)*KKEY + kbase + kk*8) << 6;
    int oi = ((o & 31) << 1) + (o >> 5);
    float2 u;
    u = unpack2(acc0); g_pre[base + oi] = u.x; g_pre[base + 64 + oi] = u.y;
    u = unpack2(acc1); g_pre[base + 128 + oi] = u.x; g_pre[base + 192 + oi] = u.y;
    u = unpack2(acc2); g_pre[base + 256 + oi] = u.x; g_pre[base + 320 + oi] = u.y;
    u = unpack2(acc3); g_pre[base + 384 + oi] = u.x; g_pre[base + 448 + oi] = u.y;
}

// ---------------- kernel Q: ball query -> padded idx + rel coords ----------
// 512 threads = 16 points/block; keypoints staged as float4 {x,y,z,|k|^2}
__global__ void __launch_bounds__(512) kQ(const float* __restrict__ kxyzg) {
    __shared__ float4 kp4[KKEY];               // 32KB
    __shared__ int idx1s[16][32], idx0s[16][16];

    const int b = blockIdx.x / 648;
    const float* kb = kxyzg + (size_t)b*KKEY*3;
    for (int i = threadIdx.x; i < KKEY; i += 512) {
        float x = kb[i*3], y = kb[i*3+1], z = kb[i*3+2];
        kp4[i] = make_float4(x, y, z, fmaf(x,x, fmaf(y,y, z*z)));
    }
    __syncthreads();

    const int w = threadIdx.x >> 5, lane = threadIdx.x & 31;
    const int p = blockIdx.x*16 + w;
    const float px = g_new_xyz[(size_t)p*3], py = g_new_xyz[(size_t)p*3+1],
                pz = g_new_xyz[(size_t)p*3+2];
    const float pn = fmaf(px,px, fmaf(py,py, pz*pz));

    const float R0 = 0.8f*0.8f, R1 = 1.6f*1.6f;
    int* l1 = idx1s[w];
    int* l0 = idx0s[w];
    int c0 = 0, c1 = 0;
    const unsigned lt = (1u << lane) - 1u;
    for (int base = 0; base < KKEY; base += 32) {
        int k = base + lane;
        float4 kk = kp4[k];
        float dot = fmaf(px,kk.x, fmaf(py,kk.y, pz*kk.z));
        float d2  = fmaf(-2.f, dot, pn + kk.w);
        bool v1 = d2 < R1, v0 = d2 < R0;
        unsigned m1 = __ballot_sync(0xffffffffu, v1);
        unsigned m0 = __ballot_sync(0xffffffffu, v0);
        if (c1 < 32 && m1) {
            if (v1) { int rk = c1 + __popc(m1 & lt); if (rk < 32) l1[rk] = k; }
            c1 = min(32, c1 + __popc(m1));
        }
        if (c0 < 16 && m0) {
            if (v0) { int rk = c0 + __popc(m0 & lt); if (rk < 16) l0[rk] = k; }
            c0 = min(16, c0 + __popc(m0));
        }
        if (c0 >= 16 && c1 >= 32) break;
    }
    __syncwarp();
    if (c1 == 0) { if (lane == 0) l1[0] = 0; c1 = 1; }
    if (c0 == 0) { if (lane == 0) l0[0] = 0; c0 = 1; }
    __syncwarp();
    {
        int f1 = l1[0], f0 = l0[0];
        if (lane >= c1) l1[lane] = f1;
        if (lane < 16 && lane >= c0) l0[lane] = f0;
    }
    __syncwarp();

    {
        int k = l1[lane];
        float4 kk = kp4[k];
        g_rel1[(size_t)p*32 + lane] =
            make_float4(kk.x-px, kk.y-py, kk.z-pz, __int_as_float(k));
        if (lane < 16) {
            int k0 = l0[lane];
            float4 k4 = kp4[k0];
            g_rel0[(size_t)p*16 + lane] =
                make_float4(k4.x-px, k4.y-py, k4.z-pz, __int_as_float(k0));
        }
    }
}

// ---------------- kernel C2: 1 pt/warp, 128-bit smem, direct epilogue -------
// (R11 kC2 verbatim — validated at 105.8-107.3us)
#define KC2_SMEM_WORDS 27008
#define OFF2_WXYZ 10240
#define OFF2_B0   10624
#define OFF2_B1   10752
#define OFF2_HW   10880
#define OFF2_REL  24704
#define HW_PITCH  144

__global__ void __launch_bounds__(384, 2) kC2(
    const float* __restrict__ w00, const float* __restrict__ b00,
    const float* __restrict__ w01, const float* __restrict__ b01,
    const float* __restrict__ w10, const float* __restrict__ b10,
    const float* __restrict__ w11, const float* __restrict__ b11)
{
    extern __shared__ float sm[];
    uint2*    wpk  = (uint2*)sm;               // [sc][kt][lane][nt pad10]
    float*    wxyz = sm + OFF2_WXYZ;
    float*    b0s  = sm + OFF2_B0;
    float*    b1s  = sm + OFF2_B1;
    unsigned* hwg  = (unsigned*)(sm + OFF2_HW);
    float4*   relg = (float4*)(sm + OFF2_REL);

    for (int i = threadIdx.x; i < 2*8*32*8; i += 384) {
        int nt = i & 7, lane2 = (i >> 3) & 31, kt = (i >> 8) & 7, sc = i >> 11;
        int gid2 = lane2 >> 2, tig2 = lane2 & 3;
        const float* W1 = sc ? w11 : w01;
        int o = nt*8 + gid2;
        int j = kt*4 + tig2;
        wpk[sc*2560 + kt*320 + lane2*10 + nt] =
            make_uint2(f2tf32(W1[o*64 + j]), f2tf32(W1[o*64 + j + 32]));
    }
    for (int i = threadIdx.x; i < 2*3*64; i += 384) {
        int sc = i / 192, t = i % 192, d = t / 64, o = t % 64;
        wxyz[i] = (sc ? w10 : w00)[o*131 + d];
    }
    if (threadIdx.x < 256) {
        int sc = (threadIdx.x >> 6) & 1, o = threadIdx.x & 63;
        if (threadIdx.x < 128) b0s[threadIdx.x] = (sc ? b10 : b00)[o];
        else                   b1s[threadIdx.x - 128] = (sc ? b11 : b01)[o];
    }
    __syncthreads();

    const int w = threadIdx.x >> 5, lane = threadIdx.x & 31;
    const int gid = lane >> 2, tig = lane & 3;
    const int p  = blockIdx.x*12 + w;
    const int b  = p / NPTS;
    const int rp = p % NPTS;
    const int n  = rp / M_GRID, mm = rp % M_GRID;

    unsigned* hw = hwg + w*8*HW_PITCH;
    float4*   relw = relg + w*48;
    const int colu = gid*16 + tig*4;

    relw[16 + lane] = g_rel1[(size_t)p*32 + lane];
    if (lane < 16) relw[lane] = g_rel0[(size_t)p*16 + lane];
    __syncwarp();

    #pragma unroll
    for (int sc = 0; sc < 2; sc++) {
        const int NPASS = sc ? 2 : 1;
        const float* preb = g_pre + ((size_t)(sc*2 + b)*KKEY << 6);
        const uint2* wps = wpk + sc*2560;
        const float* wx = wxyz + sc*192;
        const float bias0a = b0s[sc*64 + lane],  bias0b = b0s[sc*64 + lane + 32];
        const float wxa0 = wx[lane],    wxa1 = wx[64+lane],  wxa2 = wx[128+lane];
        const float wxb0 = wx[lane+32], wxb1 = wx[96+lane],  wxb2 = wx[160+lane];

        float cm0[8], cm1[8];
        #pragma unroll
        for (int nt = 0; nt < 8; nt++) { cm0[nt] = -3.4e38f; cm1[nt] = -3.4e38f; }

        for (int pass = 0; pass < NPASS; pass++) {
            const float4* relb = sc ? (relw + 16 + pass*16) : relw;
            // ---- layer 0: 16 samples, row-paired (s, s+8), STS.128 ----
            #pragma unroll
            for (int sb = 0; sb < 8; sb += 2) {
                float4 rv[4];
                float2 pr[4];
                #pragma unroll
                for (int q = 0; q < 4; q++) {
                    int si = sb + (q & 1) + ((q >> 1) << 3);
                    rv[q] = relb[si];
                    int k = __float_as_int(rv[q].w);
                    pr[q] = *(const float2*)(preb + ((size_t)k << 6) + (lane << 1));
                }
                unsigned va[4], vb[4];
                #pragma unroll
                for (int q = 0; q < 4; q++) {
                    float a = pr[q].x + bias0a;
                    a = fmaf(rv[q].x, wxa0, a);
                    a = fmaf(rv[q].y, wxa1, a);
                    a = fmaf(rv[q].z, wxa2, a);
                    float bv = pr[q].y + bias0b;
                    bv = fmaf(rv[q].x, wxb0, bv);
                    bv = fmaf(rv[q].y, wxb1, bv);
                    bv = fmaf(rv[q].z, wxb2, bv);
                    va[q] = f2tf32(fmaxf(a, 0.f));
                    vb[q] = f2tf32(fmaxf(bv, 0.f));
                }
                *(uint4*)(hw + (sb  )*HW_PITCH + colu) =
                    make_uint4(va[0], va[2], vb[0], vb[2]);
                *(uint4*)(hw + (sb+1)*HW_PITCH + colu) =
                    make_uint4(va[1], va[3], vb[1], vb[3]);
            }
            __syncwarp();

            // ---- layer 1 MMA: a = 1 LDS.128, b = 4 LDS.128 per kt ----
            float acc[8][4];
            #pragma unroll
            for (int nt = 0; nt < 8; nt++)
                acc[nt][0] = acc[nt][1] = acc[nt][2] = acc[nt][3] = 0.f;
            #pragma unroll
            for (int kt = 0; kt < 8; kt++) {
                uint4 af = *(const uint4*)(hw + gid*HW_PITCH + kt*16 + tig*4);
                const uint2* wk = wps + kt*320 + lane*10;
                #pragma unroll
                for (int ntp = 0; ntp < 4; ntp++) {
                    uint4 bp = *(const uint4*)(wk + ntp*2);
                    mma_tf32(acc[2*ntp],   af.x, af.y, af.z, af.w, bp.x, bp.y);
                    mma_tf32(acc[2*ntp+1], af.x, af.y, af.z, af.w, bp.z, bp.w);
                }
            }
            #pragma unroll
            for (int nt = 0; nt < 8; nt++) {
                cm0[nt] = fmaxf(cm0[nt], fmaxf(acc[nt][0], acc[nt][2]));
                cm1[nt] = fmaxf(cm1[nt], fmaxf(acc[nt][1], acc[nt][3]));
            }
            __syncwarp();
        }

        // reduce across row-groups (lane bits 2..4)
        #pragma unroll
        for (int off = 4; off <= 16; off <<= 1) {
            #pragma unroll
            for (int nt = 0; nt < 8; nt++) {
                cm0[nt] = fmaxf(cm0[nt], __shfl_xor_sync(0xffffffffu, cm0[nt], off));
                cm1[nt] = fmaxf(cm1[nt], __shfl_xor_sync(0xffffffffu, cm1[nt], off));
            }
        }
        size_t rowb = (size_t)(b*NPROP + n)*QDIM + (size_t)sc*64*M_GRID + mm;
        if (gid == 0) {
            #pragma unroll
            for (int nt = 0; nt < 8; nt++) {
                int o0 = nt*8 + tig*2;
                float v0 = fmaxf(cm0[nt] + b1s[sc*64 + o0],     0.f);
                float v1 = fmaxf(cm1[nt] + b1s[sc*64 + o0 + 1], 0.f);
                g_pooled[rowb + (size_t)o0*M_GRID]     = v0;
                g_pooled[rowb + (size_t)(o0+1)*M_GRID] = v1;
            }
        }
    }
}

// ---------------- kernel D: K-split tf32 MMA, 32-k tiles (R13, validated) ---
#define KD_KT 32
#define XDP 40
__global__ void __launch_bounds__(384) kD(const float* __restrict__ w0) {
    __shared__ unsigned xs[96*XDP];
    __shared__ unsigned ws[64*XDP];
    const int tid = threadIdx.x;
    const int w = tid >> 5, lane = tid & 31;
    const int gid = lane >> 2, tig = lane & 3;
    const int rg = w % 6, cg = w / 6;
    const int colbase = blockIdx.x * 64;
    const int kg0 = blockIdx.y * KCHUNK;

    const int frow = tid >> 2;
    const int fq   = (tid & 3) << 2;
    const int slotb = ((fq & 4) << 1) + (fq >> 3);

    const float* xg = g_pooled + (size_t)frow*QDIM + kg0 + fq;
    const float* wg = w0 + (size_t)(colbase + (tid >> 2))*QDIM + kg0 + ((tid & 3) << 2);

    float4 xv0 = *(const float4*)xg;
    float4 xv1 = *(const float4*)(xg + 16);
    float4 wv0 = make_float4(0.f,0.f,0.f,0.f), wv1 = wv0;
    if (tid < 256) { wv0 = *(const float4*)wg; wv1 = *(const float4*)(wg + 16); }

    float acc[4][4] = {};
    const int NT = KCHUNK / KD_KT;              // 8
    for (int t = 0; t < NT; t++) {
        __syncthreads();
        {
            unsigned* d = xs + frow*XDP + slotb;
            d[0]  = f2tf32(xv0.x); d[2]  = f2tf32(xv0.y);
            d[4]  = f2tf32(xv0.z); d[6]  = f2tf32(xv0.w);
            d[20] = f2tf32(xv1.x); d[22] = f2tf32(xv1.y);
            d[24] = f2tf32(xv1.z); d[26] = f2tf32(xv1.w);
        }
        if (tid < 256) {
            unsigned* d = ws + (tid >> 2)*XDP + slotb;
            d[0]  = f2tf32(wv0.x); d[2]  = f2tf32(wv0.y);
            d[4]  = f2tf32(wv0.z); d[6]  = f2tf32(wv0.w);
            d[20] = f2tf32(wv1.x); d[22] = f2tf32(wv1.y);
            d[24] = f2tf32(wv1.z); d[26] = f2tf32(wv1.w);
        }
        __syncthreads();
        if (t + 1 < NT) {
            int dlt = (t + 1) * KD_KT;
            xv0 = *(const float4*)(xg + dlt);
            xv1 = *(const float4*)(xg + dlt + 16);
            if (tid < 256) {
                wv0 = *(const float4*)(wg + dlt);
                wv1 = *(const float4*)(wg + dlt + 16);
            }
        }
        #pragma unroll
        for (int kt = 0; kt < 4; kt++) {
            int off = (kt >> 1)*20 + (kt & 1)*8 + tig*2;
            uint2 alo = *(const uint2*)(xs + (rg*16 + gid    )*XDP + off);
            uint2 ahi = *(const uint2*)(xs + (rg*16 + gid + 8)*XDP + off);
            #pragma unroll
            for (int nt = 0; nt < 4; nt++) {
                uint2 bb = *(const uint2*)(ws + (cg*32 + nt*8 + gid)*XDP + off);
                mma_tf32(acc[nt], alo.x, ahi.x, alo.y, ahi.y, bb.x, bb.y);
            }
        }
    }
    #pragma unroll
    for (int nt = 0; nt < 4; nt++) {
        int col = colbase + cg*32 + nt*8 + tig*2;
        int row = rg*16 + gid;
        float* pp = g_partial + ((size_t)blockIdx.y*96 + row)*256 + col;
        *(float2*)pp             = make_float2(acc[nt][0], acc[nt][1]);
        *(float2*)(pp + 8*256)   = make_float2(acc[nt][2], acc[nt][3]);
    }
}

// ---------------- kernel E: reduce + relu + 256x256 GEMM + relu ------------
__global__ void __launch_bounds__(256) kE(const float* __restrict__ rb0,
                                          const float* __restrict__ rw1,
                                          const float* __restrict__ rb1,
                                          float* __restrict__ out) {
    __shared__ float h2s[256];
    __shared__ float w1s[256*33];
    const int row = blockIdx.x;
    const int o = threadIdx.x;
    float s = rb0[o];
    #pragma unroll 4
    for (int ks = 0; ks < KSPLIT; ks++)
        s += g_partial[((size_t)ks*96 + row)*256 + o];
    h2s[o] = fmaxf(s, 0.f);
    __syncthreads();

    float acc = rb1[o];
    for (int jt = 0; jt < 256; jt += 32) {
        for (int i = threadIdx.x; i < 8192; i += 256) {
            int oo = i >> 5, jj = i & 31;
            w1s[oo*33 + jj] = rw1[(size_t)oo*256 + jt + jj];
        }
        __syncthreads();
        #pragma unroll
        for (int jj = 0; jj < 32; jj++)
            acc = fmaf(h2s[jt + jj], w1s[o*33 + jj], acc);
        __syncthreads();
    }
    out[(size_t)row*256 + o] = fmaxf(acc, 0.f);
}

// ---------------- launch ----------------
extern "C" void kernel_launch(void* const* d_in, const int* in_sizes, int n_in,
                              void* d_out, int out_size) {
    const float* proposals = (const float*)d_in[0];
    const float* kxyz      = (const float*)d_in[1];
    const float* kfeat     = (const float*)d_in[2];
    const float* gnoise    = (const float*)d_in[3];
    const float* w00 = (const float*)d_in[4];
    const float* b00 = (const float*)d_in[5];
    const float* w01 = (const float*)d_in[6];
    const float* b01 = (const float*)d_in[7];
    const float* w10 = (const float*)d_in[8];
    const float* b10 = (const float*)d_in[9];
    const float* w11 = (const float*)d_in[10];
    const float* b11 = (const float*)d_in[11];
    const float* rw0 = (const float*)d_in[12];
    const float* rb0 = (const float*)d_in[13];
    const float* rw1 = (const float*)d_in[14];
    const float* rb1 = (const float*)d_in[15];
    float* out = (float*)d_out;

    cudaFuncSetAttribute(kC2, cudaFuncAttributeMaxDynamicSharedMemorySize,
                         KC2_SMEM_WORDS * 4);

    kA<<<(NTOT + 255)/256, 256>>>(proposals, gnoise);
    kB<<<dim3(KKEY/32, 4), 256>>>(kfeat, w00, w10);
    kQ<<<NTOT/16, 512>>>(kxyz);
    kC2<<<NTOT/12, 384, KC2_SMEM_WORDS * 4>>>(w00, b00, w01, b01,
                                              w10, b10, w11, b11);
    kD<<<dim3(4, KSPLIT), 384>>>(rw0);
    kE<<<96, 256>>>(rb0, rw1, rb1, out);
}

// round 15
// speedup vs baseline: 1.1045x; 1.0691x over previous
#include <cuda_runtime.h>
#include <math.h>

#define KKEY   2048
#define CFEAT  128
#define M_GRID 216
#define NPROP  48
#define NPTS   (NPROP*M_GRID)      // 10368 per batch
#define NTOT   (2*NPTS)            // 20736
#define QDIM   (128*M_GRID)        // 27648
#define KSPLIT 108
#define KCHUNK 256

typedef unsigned long long ull;

__device__ __forceinline__ ull pack2(float lo, float hi) {
    ull r; asm("mov.b64 %0, {%1, %2};" : "=l"(r) : "f"(lo), "f"(hi)); return r;
}
__device__ __forceinline__ ull ffma2(ull a, ull b, ull c) {
    ull d; asm("fma.rn.f32x2 %0, %1, %2, %3;" : "=l"(d) : "l"(a), "l"(b), "l"(c)); return d;
}
__device__ __forceinline__ float2 unpack2(ull v) {
    float2 f; asm("mov.b64 {%0, %1}, %2;" : "=f"(f.x), "=f"(f.y) : "l"(v)); return f;
}
__device__ __forceinline__ unsigned f2tf32(float v) {
    unsigned u; asm("cvt.rna.tf32.f32 %0, %1;" : "=r"(u) : "f"(v)); return u;
}
__device__ __forceinline__ void mma_tf32(float d[4], const unsigned a0, const unsigned a1,
                                         const unsigned a2, const unsigned a3,
                                         const unsigned b0, const unsigned b1) {
    asm("mma.sync.aligned.m16n8k8.row.col.f32.tf32.tf32.f32 "
        "{%0,%1,%2,%3}, {%4,%5,%6,%7}, {%8,%9}, {%0,%1,%2,%3};"
        : "+f"(d[0]), "+f"(d[1]), "+f"(d[2]), "+f"(d[3])
        : "r"(a0), "r"(a1), "r"(a2), "r"(a3), "r"(b0), "r"(b1));
}

// ---------------- scratch ----------------
__device__ float  g_new_xyz[NTOT*3];
__device__ float  g_pre[2*2*KKEY*64];        // [scale][b][k][interleaved o]
__device__ float4 g_rel1[NTOT*32];           // {rx,ry,rz, bitcast k}
__device__ float4 g_rel0[NTOT*16];
__device__ float  g_pooled[2*NPROP*QDIM];    // 96 x 27648, q = co*216+mm
__device__ float  g_partial[KSPLIT*96*256];

// ---------------- kernel A: grid transform -> new_xyz ----------------
__global__ void __launch_bounds__(256) kA(const float* __restrict__ prop,
                                          const float* __restrict__ gnoise) {
    int t = blockIdx.x*256 + threadIdx.x;
    if (t >= NTOT) return;
    int b = t / NPTS, r = t % NPTS;
    int n = r / M_GRID, mm = r % M_GRID;
    const float* p = prop + (size_t)(b*NPROP + n)*7;
    const float* g = gnoise + ((size_t)(b*NPROP + n)*M_GRID + mm)*3;
    float gx = g[0]*p[3], gy = g[1]*p[4], gz = g[2]*p[5];
    float c = cosf(p[6]), s = sinf(p[6]);
    float* o = g_new_xyz + (size_t)t*3;
    o[0] = c*gx - s*gy + p[0];
    o[1] = s*gx + c*gy + p[1];
    o[2] = gz + p[2];
}

// ---------------- kernel B: pre[k][o] = W0[:,3:] . feats[:,k] ----------------
__global__ void __launch_bounds__(256) kB(const float* __restrict__ feats,
                                          const float* __restrict__ w0,
                                          const float* __restrict__ w1) {
    __shared__ float Ws[CFEAT*64];
    __shared__ float fs[CFEAT*32];
    int sb = blockIdx.y; int sc = sb >> 1, b = sb & 1;
    const float* W = sc ? w1 : w0;
    for (int i = threadIdx.x; i < CFEAT*64; i += 256) {
        int c = i >> 6, o = i & 63;
        Ws[i] = W[o*131 + 3 + c];
    }
    int kbase = blockIdx.x * 32;
    const float* fb = feats + (size_t)b*CFEAT*KKEY + kbase;
    for (int i = threadIdx.x; i < CFEAT*8; i += 256) {
        int c = i >> 3, q = i & 7;
        *(float4*)(fs + c*32 + q*4) = *(const float4*)(fb + (size_t)c*KKEY + q*4);
    }
    __syncthreads();

    int o  = threadIdx.x & 63;
    int kk = threadIdx.x >> 6;
    ull acc0 = 0, acc1 = 0, acc2 = 0, acc3 = 0;
    #pragma unroll 4
    for (int c = 0; c < CFEAT; c++) {
        float w = Ws[c*64 + o];
        ull wd = pack2(w, w);
        const ull* f = (const ull*)(fs + c*32 + kk*8);
        acc0 = ffma2(wd, f[0], acc0);
        acc1 = ffma2(wd, f[1], acc1);
        acc2 = ffma2(wd, f[2], acc2);
        acc3 = ffma2(wd, f[3], acc3);
    }
    size_t base = ((size_t)(sc*2 + b)*KKEY + kbase + kk*8) << 6;
    int oi = ((o & 31) << 1) + (o >> 5);
    float2 u;
    u = unpack2(acc0); g_pre[base + oi] = u.x; g_pre[base + 64 + oi] = u.y;
    u = unpack2(acc1); g_pre[base + 128 + oi] = u.x; g_pre[base + 192 + oi] = u.y;
    u = unpack2(acc2); g_pre[base + 256 + oi] = u.x; g_pre[base + 320 + oi] = u.y;
    u = unpack2(acc3); g_pre[base + 384 + oi] = u.x; g_pre[base + 448 + oi] = u.y;
}

// ---------------- kernel Q: ball query -> padded idx + rel coords ----------
// 1024 threads = 32 points/block (halves keypoint staging per point)
__global__ void __launch_bounds__(1024) kQ(const float* __restrict__ kxyzg) {
    __shared__ float4 kp4[KKEY];               // {x,y,z,|k|^2}, 32KB
    __shared__ int idx1s[32][32], idx0s[32][16];

    const int b = blockIdx.x / 324;            // 324 blocks per batch
    const float* kb = kxyzg + (size_t)b*KKEY*3;
    for (int i = threadIdx.x; i < KKEY; i += 1024) {
        float x = kb[i*3], y = kb[i*3+1], z = kb[i*3+2];
        kp4[i] = make_float4(x, y, z, fmaf(x,x, fmaf(y,y, z*z)));
    }
    __syncthreads();

    const int w = threadIdx.x >> 5, lane = threadIdx.x & 31;
    const int p = blockIdx.x*32 + w;
    const float px = g_new_xyz[(size_t)p*3], py = g_new_xyz[(size_t)p*3+1],
                pz = g_new_xyz[(size_t)p*3+2];
    const float pn = fmaf(px,px, fmaf(py,py, pz*pz));

    const float R0 = 0.8f*0.8f, R1 = 1.6f*1.6f;
    int* l1 = idx1s[w];
    int* l0 = idx0s[w];
    int c0 = 0, c1 = 0;
    const unsigned lt = (1u << lane) - 1u;
    for (int base = 0; base < KKEY; base += 32) {
        int k = base + lane;
        float4 kk = kp4[k];
        float dot = fmaf(px,kk.x, fmaf(py,kk.y, pz*kk.z));
        float d2  = fmaf(-2.f, dot, pn + kk.w);
        bool v1 = d2 < R1, v0 = d2 < R0;
        unsigned m1 = __ballot_sync(0xffffffffu, v1);
        unsigned m0 = __ballot_sync(0xffffffffu, v0);
        if (c1 < 32 && m1) {
            if (v1) { int rk = c1 + __popc(m1 & lt); if (rk < 32) l1[rk] = k; }
            c1 = min(32, c1 + __popc(m1));
        }
        if (c0 < 16 && m0) {
            if (v0) { int rk = c0 + __popc(m0 & lt); if (rk < 16) l0[rk] = k; }
            c0 = min(16, c0 + __popc(m0));
        }
        if (c0 >= 16 && c1 >= 32) break;
    }
    __syncwarp();
    if (c1 == 0) { if (lane == 0) l1[0] = 0; c1 = 1; }
    if (c0 == 0) { if (lane == 0) l0[0] = 0; c0 = 1; }
    __syncwarp();
    {
        int f1 = l1[0], f0 = l0[0];
        if (lane >= c1) l1[lane] = f1;
        if (lane < 16 && lane >= c0) l0[lane] = f0;
    }
    __syncwarp();

    {
        int k = l1[lane];
        float4 kk = kp4[k];
        g_rel1[(size_t)p*32 + lane] =
            make_float4(kk.x-px, kk.y-py, kk.z-pz, __int_as_float(k));
        if (lane < 16) {
            int k0 = l0[lane];
            float4 k4 = kp4[k0];
            g_rel0[(size_t)p*16 + lane] =
                make_float4(k4.x-px, k4.y-py, k4.z-pz, __int_as_float(k0));
        }
    }
}

// ---------------- kernel C2: 1 pt/warp, 128-bit smem, direct epilogue -------
// (R11/R14 kC2 verbatim — validated at 105.8-107.6us)
#define KC2_SMEM_WORDS 27008
#define OFF2_WXYZ 10240
#define OFF2_B0   10624
#define OFF2_B1   10752
#define OFF2_HW   10880
#define OFF2_REL  24704
#define HW_PITCH  144

__global__ void __launch_bounds__(384, 2) kC2(
    const float* __restrict__ w00, const float* __restrict__ b00,
    const float* __restrict__ w01, const float* __restrict__ b01,
    const float* __restrict__ w10, const float* __restrict__ b10,
    const float* __restrict__ w11, const float* __restrict__ b11)
{
    extern __shared__ float sm[];
    uint2*    wpk  = (uint2*)sm;               // [sc][kt][lane][nt pad10]
    float*    wxyz = sm + OFF2_WXYZ;
    float*    b0s  = sm + OFF2_B0;
    float*    b1s  = sm + OFF2_B1;
    unsigned* hwg  = (unsigned*)(sm + OFF2_HW);
    float4*   relg = (float4*)(sm + OFF2_REL);

    for (int i = threadIdx.x; i < 2*8*32*8; i += 384) {
        int nt = i & 7, lane2 = (i >> 3) & 31, kt = (i >> 8) & 7, sc = i >> 11;
        int gid2 = lane2 >> 2, tig2 = lane2 & 3;
        const float* W1 = sc ? w11 : w01;
        int o = nt*8 + gid2;
        int j = kt*4 + tig2;
        wpk[sc*2560 + kt*320 + lane2*10 + nt] =
            make_uint2(f2tf32(W1[o*64 + j]), f2tf32(W1[o*64 + j + 32]));
    }
    for (int i = threadIdx.x; i < 2*3*64; i += 384) {
        int sc = i / 192, t = i % 192, d = t / 64, o = t % 64;
        wxyz[i] = (sc ? w10 : w00)[o*131 + d];
    }
    if (threadIdx.x < 256) {
        int sc = (threadIdx.x >> 6) & 1, o = threadIdx.x & 63;
        if (threadIdx.x < 128) b0s[threadIdx.x] = (sc ? b10 : b00)[o];
        else                   b1s[threadIdx.x - 128] = (sc ? b11 : b01)[o];
    }
    __syncthreads();

    const int w = threadIdx.x >> 5, lane = threadIdx.x & 31;
    const int gid = lane >> 2, tig = lane & 3;
    const int p  = blockIdx.x*12 + w;
    const int b  = p / NPTS;
    const int rp = p % NPTS;
    const int n  = rp / M_GRID, mm = rp % M_GRID;

    unsigned* hw = hwg + w*8*HW_PITCH;
    float4*   relw = relg + w*48;
    const int colu = gid*16 + tig*4;

    relw[16 + lane] = g_rel1[(size_t)p*32 + lane];
    if (lane < 16) relw[lane] = g_rel0[(size_t)p*16 + lane];
    __syncwarp();

    #pragma unroll
    for (int sc = 0; sc < 2; sc++) {
        const int NPASS = sc ? 2 : 1;
        const float* preb = g_pre + ((size_t)(sc*2 + b)*KKEY << 6);
        const uint2* wps = wpk + sc*2560;
        const float* wx = wxyz + sc*192;
        const float bias0a = b0s[sc*64 + lane],  bias0b = b0s[sc*64 + lane + 32];
        const float wxa0 = wx[lane],    wxa1 = wx[64+lane],  wxa2 = wx[128+lane];
        const float wxb0 = wx[lane+32], wxb1 = wx[96+lane],  wxb2 = wx[160+lane];

        float cm0[8], cm1[8];
        #pragma unroll
        for (int nt = 0; nt < 8; nt++) { cm0[nt] = -3.4e38f; cm1[nt] = -3.4e38f; }

        for (int pass = 0; pass < NPASS; pass++) {
            const float4* relb = sc ? (relw + 16 + pass*16) : relw;
            // ---- layer 0: 16 samples, row-paired (s, s+8), STS.128 ----
            #pragma unroll
            for (int sb = 0; sb < 8; sb += 2) {
                float4 rv[4];
                float2 pr[4];
                #pragma unroll
                for (int q = 0; q < 4; q++) {
                    int si = sb + (q & 1) + ((q >> 1) << 3);
                    rv[q] = relb[si];
                    int k = __float_as_int(rv[q].w);
                    pr[q] = *(const float2*)(preb + ((size_t)k << 6) + (lane << 1));
                }
                unsigned va[4], vb[4];
                #pragma unroll
                for (int q = 0; q < 4; q++) {
                    float a = pr[q].x + bias0a;
                    a = fmaf(rv[q].x, wxa0, a);
                    a = fmaf(rv[q].y, wxa1, a);
                    a = fmaf(rv[q].z, wxa2, a);
                    float bv = pr[q].y + bias0b;
                    bv = fmaf(rv[q].x, wxb0, bv);
                    bv = fmaf(rv[q].y, wxb1, bv);
                    bv = fmaf(rv[q].z, wxb2, bv);
                    va[q] = f2tf32(fmaxf(a, 0.f));
                    vb[q] = f2tf32(fmaxf(bv, 0.f));
                }
                *(uint4*)(hw + (sb  )*HW_PITCH + colu) =
                    make_uint4(va[0], va[2], vb[0], vb[2]);
                *(uint4*)(hw + (sb+1)*HW_PITCH + colu) =
                    make_uint4(va[1], va[3], vb[1], vb[3]);
            }
            __syncwarp();

            // ---- layer 1 MMA: a = 1 LDS.128, b = 4 LDS.128 per kt ----
            float acc[8][4];
            #pragma unroll
            for (int nt = 0; nt < 8; nt++)
                acc[nt][0] = acc[nt][1] = acc[nt][2] = acc[nt][3] = 0.f;
            #pragma unroll
            for (int kt = 0; kt < 8; kt++) {
                uint4 af = *(const uint4*)(hw + gid*HW_PITCH + kt*16 + tig*4);
                const uint2* wk = wps + kt*320 + lane*10;
                #pragma unroll
                for (int ntp = 0; ntp < 4; ntp++) {
                    uint4 bp = *(const uint4*)(wk + ntp*2);
                    mma_tf32(acc[2*ntp],   af.x, af.y, af.z, af.w, bp.x, bp.y);
                    mma_tf32(acc[2*ntp+1], af.x, af.y, af.z, af.w, bp.z, bp.w);
                }
            }
            #pragma unroll
            for (int nt = 0; nt < 8; nt++) {
                cm0[nt] = fmaxf(cm0[nt], fmaxf(acc[nt][0], acc[nt][2]));
                cm1[nt] = fmaxf(cm1[nt], fmaxf(acc[nt][1], acc[nt][3]));
            }
            __syncwarp();
        }

        // reduce across row-groups (lane bits 2..4)
        #pragma unroll
        for (int off = 4; off <= 16; off <<= 1) {
            #pragma unroll
            for (int nt = 0; nt < 8; nt++) {
                cm0[nt] = fmaxf(cm0[nt], __shfl_xor_sync(0xffffffffu, cm0[nt], off));
                cm1[nt] = fmaxf(cm1[nt], __shfl_xor_sync(0xffffffffu, cm1[nt], off));
            }
        }
        size_t rowb = (size_t)(b*NPROP + n)*QDIM + (size_t)sc*64*M_GRID + mm;
        if (gid == 0) {
            #pragma unroll
            for (int nt = 0; nt < 8; nt++) {
                int o0 = nt*8 + tig*2;
                float v0 = fmaxf(cm0[nt] + b1s[sc*64 + o0],     0.f);
                float v1 = fmaxf(cm1[nt] + b1s[sc*64 + o0 + 1], 0.f);
                g_pooled[rowb + (size_t)o0*M_GRID]     = v0;
                g_pooled[rowb + (size_t)(o0+1)*M_GRID] = v1;
            }
        }
    }
}

// ---------------- kernel D: K-split tf32 MMA, 32-k tiles (R13, validated) ---
#define KD_KT 32
#define XDP 40
__global__ void __launch_bounds__(384) kD(const float* __restrict__ w0) {
    __shared__ unsigned xs[96*XDP];
    __shared__ unsigned ws[64*XDP];
    const int tid = threadIdx.x;
    const int w = tid >> 5, lane = tid & 31;
    const int gid = lane >> 2, tig = lane & 3;
    const int rg = w % 6, cg = w / 6;
    const int colbase = blockIdx.x * 64;
    const int kg0 = blockIdx.y * KCHUNK;

    const int frow = tid >> 2;
    const int fq   = (tid & 3) << 2;
    const int slotb = ((fq & 4) << 1) + (fq >> 3);

    const float* xg = g_pooled + (size_t)frow*QDIM + kg0 + fq;
    const float* wg = w0 + (size_t)(colbase + (tid >> 2))*QDIM + kg0 + ((tid & 3) << 2);

    float4 xv0 = *(const float4*)xg;
    float4 xv1 = *(const float4*)(xg + 16);
    float4 wv0 = make_float4(0.f,0.f,0.f,0.f), wv1 = wv0;
    if (tid < 256) { wv0 = *(const float4*)wg; wv1 = *(const float4*)(wg + 16); }

    float acc[4][4] = {};
    const int NT = KCHUNK / KD_KT;              // 8
    for (int t = 0; t < NT; t++) {
        __syncthreads();
        {
            unsigned* d = xs + frow*XDP + slotb;
            d[0]  = f2tf32(xv0.x); d[2]  = f2tf32(xv0.y);
            d[4]  = f2tf32(xv0.z); d[6]  = f2tf32(xv0.w);
            d[20] = f2tf32(xv1.x); d[22] = f2tf32(xv1.y);
            d[24] = f2tf32(xv1.z); d[26] = f2tf32(xv1.w);
        }
        if (tid < 256) {
            unsigned* d = ws + (tid >> 2)*XDP + slotb;
            d[0]  = f2tf32(wv0.x); d[2]  = f2tf32(wv0.y);
            d[4]  = f2tf32(wv0.z); d[6]  = f2tf32(wv0.w);
            d[20] = f2tf32(wv1.x); d[22] = f2tf32(wv1.y);
            d[24] = f2tf32(wv1.z); d[26] = f2tf32(wv1.w);
        }
        __syncthreads();
        if (t + 1 < NT) {
            int dlt = (t + 1) * KD_KT;
            xv0 = *(const float4*)(xg + dlt);
            xv1 = *(const float4*)(xg + dlt + 16);
            if (tid < 256) {
                wv0 = *(const float4*)(wg + dlt);
                wv1 = *(const float4*)(wg + dlt + 16);
            }
        }
        #pragma unroll
        for (int kt = 0; kt < 4; kt++) {
            int off = (kt >> 1)*20 + (kt & 1)*8 + tig*2;
            uint2 alo = *(const uint2*)(xs + (rg*16 + gid    )*XDP + off);
            uint2 ahi = *(const uint2*)(xs + (rg*16 + gid + 8)*XDP + off);
            #pragma unroll
            for (int nt = 0; nt < 4; nt++) {
                uint2 bb = *(const uint2*)(ws + (cg*32 + nt*8 + gid)*XDP + off);
                mma_tf32(acc[nt], alo.x, ahi.x, alo.y, ahi.y, bb.x, bb.y);
            }
        }
    }
    #pragma unroll
    for (int nt = 0; nt < 4; nt++) {
        int col = colbase + cg*32 + nt*8 + tig*2;
        int row = rg*16 + gid;
        float* pp = g_partial + ((size_t)blockIdx.y*96 + row)*256 + col;
        *(float2*)pp             = make_float2(acc[nt][0], acc[nt][1]);
        *(float2*)(pp + 8*256)   = make_float2(acc[nt][2], acc[nt][3]);
    }
}

// ---------------- kernel E: parallel reduce + relu + 256x256 GEMM + relu ----
// 1024 threads: thread (o = tid&255, q = tid>>8) sums 27 partials; smem
// combine; 256x256 GEMM staged by all threads, computed by first 256.
__global__ void __launch_bounds__(1024) kE(const float* __restrict__ rb0,
                                           const float* __restrict__ rw1,
                                           const float* __restrict__ rb1,
                                           float* __restrict__ out) {
    __shared__ float hpart[4][256];
    __shared__ float h2s[256];
    __shared__ float w1s[256*33];
    const int row = blockIdx.x;
    const int o = threadIdx.x & 255, q = threadIdx.x >> 8;

    float s = 0.f;
    #pragma unroll 9
    for (int i = 0; i < 27; i++) {
        int ks = q*27 + i;
        s += g_partial[((size_t)ks*96 + row)*256 + o];
    }
    hpart[q][o] = s;
    __syncthreads();
    if (threadIdx.x < 256) {
        float t = rb0[o] + ((hpart[0][o] + hpart[1][o]) + (hpart[2][o] + hpart[3][o]));
        h2s[o] = fmaxf(t, 0.f);
    }
    __syncthreads();

    float acc = (threadIdx.x < 256) ? rb1[o] : 0.f;
    for (int jt = 0; jt < 256; jt += 32) {
        for (int i = threadIdx.x; i < 8192; i += 1024) {
            int oo = i >> 5, jj = i & 31;
            w1s[oo*33 + jj] = rw1[(size_t)oo*256 + jt + jj];
        }
        __syncthreads();
        if (threadIdx.x < 256) {
            #pragma unroll
            for (int jj = 0; jj < 32; jj++)
                acc = fmaf(h2s[jt + jj], w1s[o*33 + jj], acc);
        }
        __syncthreads();
    }
    if (threadIdx.x < 256)
        out[(size_t)row*256 + o] = fmaxf(acc, 0.f);
}

// ---------------- launch ----------------
extern "C" void kernel_launch(void* const* d_in, const int* in_sizes, int n_in,
                              void* d_out, int out_size) {
    const float* proposals = (const float*)d_in[0];
    const float* kxyz      = (const float*)d_in[1];
    const float* kfeat     = (const float*)d_in[2];
    const float* gnoise    = (const float*)d_in[3];
    const float* w00 = (const float*)d_in[4];
    const float* b00 = (const float*)d_in[5];
    const float* w01 = (const float*)d_in[6];
    const float* b01 = (const float*)d_in[7];
    const float* w10 = (const float*)d_in[8];
    const float* b10 = (const float*)d_in[9];
    const float* w11 = (const float*)d_in[10];
    const float* b11 = (const float*)d_in[11];
    const float* rw0 = (const float*)d_in[12];
    const float* rb0 = (const float*)d_in[13];
    const float* rw1 = (const float*)d_in[14];
    const float* rb1 = (const float*)d_in[15];
    float* out = (float*)d_out;

    cudaFuncSetAttribute(kC2, cudaFuncAttributeMaxDynamicSharedMemorySize,
                         KC2_SMEM_WORDS * 4);

    kA<<<(NTOT + 255)/256, 256>>>(proposals, gnoise);
    kB<<<dim3(KKEY/32, 4), 256>>>(kfeat, w00, w10);
    kQ<<<NTOT/32, 1024>>>(kxyz);
    kC2<<<NTOT/12, 384, KC2_SMEM_WORDS * 4>>>(w00, b00, w01, b01,
                                              w10, b10, w11, b11);
    kD<<<dim3(4, KSPLIT), 384>>>(rw0);
    kE<<<96, 1024>>>(rb0, rw1, rb1, out);
}

// round 16
// speedup vs baseline: 1.1546x; 1.0454x over previous
#include <cuda_runtime.h>
#include <math.h>

#define KKEY   2048
#define CFEAT  128
#define M_GRID 216
#define NPROP  48
#define NPTS   (NPROP*M_GRID)      // 10368 per batch
#define NTOT   (2*NPTS)            // 20736
#define QDIM   (128*M_GRID)        // 27648
#define KSPLIT 72
#define KCHUNK 384

typedef unsigned long long ull;

__device__ __forceinline__ ull pack2(float lo, float hi) {
    ull r; asm("mov.b64 %0, {%1, %2};" : "=l"(r) : "f"(lo), "f"(hi)); return r;
}
__device__ __forceinline__ ull ffma2(ull a, ull b, ull c) {
    ull d; asm("fma.rn.f32x2 %0, %1, %2, %3;" : "=l"(d) : "l"(a), "l"(b), "l"(c)); return d;
}
__device__ __forceinline__ float2 unpack2(ull v) {
    float2 f; asm("mov.b64 {%0, %1}, %2;" : "=f"(f.x), "=f"(f.y) : "l"(v)); return f;
}
__device__ __forceinline__ unsigned f2tf32(float v) {
    unsigned u; asm("cvt.rna.tf32.f32 %0, %1;" : "=r"(u) : "f"(v)); return u;
}
__device__ __forceinline__ void mma_tf32(float d[4], const unsigned a0, const unsigned a1,
                                         const unsigned a2, const unsigned a3,
                                         const unsigned b0, const unsigned b1) {
    asm("mma.sync.aligned.m16n8k8.row.col.f32.tf32.tf32.f32 "
        "{%0,%1,%2,%3}, {%4,%5,%6,%7}, {%8,%9}, {%0,%1,%2,%3};"
        : "+f"(d[0]), "+f"(d[1]), "+f"(d[2]), "+f"(d[3])
        : "r"(a0), "r"(a1), "r"(a2), "r"(a3), "r"(b0), "r"(b1));
}

// ---------------- scratch ----------------
__device__ float  g_new_xyz[NTOT*3];
__device__ float  g_pre[2*2*KKEY*64];        // [scale][b][k][interleaved o]
__device__ float4 g_rel1[NTOT*32];           // {rx,ry,rz, bitcast k}
__device__ float4 g_rel0[NTOT*16];
__device__ float  g_pooled[2*NPROP*QDIM];    // 96 x 27648, q = co*216+mm
__device__ float  g_partial[KSPLIT*96*256];

// ---------------- kernel A: grid transform -> new_xyz ----------------
__global__ void __launch_bounds__(256) kA(const float* __restrict__ prop,
                                          const float* __restrict__ gnoise) {
    int t = blockIdx.x*256 + threadIdx.x;
    if (t >= NTOT) return;
    int b = t / NPTS, r = t % NPTS;
    int n = r / M_GRID, mm = r % M_GRID;
    const float* p = prop + (size_t)(b*NPROP + n)*7;
    const float* g = gnoise + ((size_t)(b*NPROP + n)*M_GRID + mm)*3;
    float gx = g[0]*p[3], gy = g[1]*p[4], gz = g[2]*p[5];
    float c = cosf(p[6]), s = sinf(p[6]);
    float* o = g_new_xyz + (size_t)t*3;
    o[0] = c*gx - s*gy + p[0];
    o[1] = s*gx + c*gy + p[1];
    o[2] = gz + p[2];
}

// ---------------- kernel B: pre[k][o] = W0[:,3:] . feats[:,k] ----------------
__global__ void __launch_bounds__(256) kB(const float* __restrict__ feats,
                                          const float* __restrict__ w0,
                                          const float* __restrict__ w1) {
    __shared__ float Ws[CFEAT*64];
    __shared__ float fs[CFEAT*32];
    int sb = blockIdx.y; int sc = sb >> 1, b = sb & 1;
    const float* W = sc ? w1 : w0;
    for (int i = threadIdx.x; i < CFEAT*64; i += 256) {
        int c = i >> 6, o = i & 63;
        Ws[i] = W[o*131 + 3 + c];
    }
    int kbase = blockIdx.x * 32;
    const float* fb = feats + (size_t)b*CFEAT*KKEY + kbase;
    for (int i = threadIdx.x; i < CFEAT*8; i += 256) {
        int c = i >> 3, q = i & 7;
        *(float4*)(fs + c*32 + q*4) = *(const float4*)(fb + (size_t)c*KKEY + q*4);
    }
    __syncthreads();

    int o  = threadIdx.x & 63;
    int kk = threadIdx.x >> 6;
    ull acc0 = 0, acc1 = 0, acc2 = 0, acc3 = 0;
    #pragma unroll 4
    for (int c = 0; c < CFEAT; c++) {
        float w = Ws[c*64 + o];
        ull wd = pack2(w, w);
        const ull* f = (const ull*)(fs + c*32 + kk*8);
        acc0 = ffma2(wd, f[0], acc0);
        acc1 = ffma2(wd, f[1], acc1);
        acc2 = ffma2(wd, f[2], acc2);
        acc3 = ffma2(wd, f[3], acc3);
    }
    size_t base = ((size_t)(sc*2 + b)*KKEY + kbase + kk*8) << 6;
    int oi = ((o & 31) << 1) + (o >> 5);
    float2 u;
    u = unpack2(acc0); g_pre[base + oi] = u.x; g_pre[base + 64 + oi] = u.y;
    u = unpack2(acc1); g_pre[base + 128 + oi] = u.x; g_pre[base + 192 + oi] = u.y;
    u = unpack2(acc2); g_pre[base + 256 + oi] = u.x; g_pre[base + 320 + oi] = u.y;
    u = unpack2(acc3); g_pre[base + 384 + oi] = u.x; g_pre[base + 448 + oi] = u.y;
}

// ---------------- kernel Q: ball query -> padded idx + rel coords ----------
// 1024 threads = 32 points/block
__global__ void __launch_bounds__(1024) kQ(const float* __restrict__ kxyzg) {
    __shared__ float4 kp4[KKEY];               // {x,y,z,|k|^2}, 32KB
    __shared__ int idx1s[32][32], idx0s[32][16];

    const int b = blockIdx.x / 324;
    const float* kb = kxyzg + (size_t)b*KKEY*3;
    for (int i = threadIdx.x; i < KKEY; i += 1024) {
        float x = kb[i*3], y = kb[i*3+1], z = kb[i*3+2];
        kp4[i] = make_float4(x, y, z, fmaf(x,x, fmaf(y,y, z*z)));
    }
    __syncthreads();

    const int w = threadIdx.x >> 5, lane = threadIdx.x & 31;
    const int p = blockIdx.x*32 + w;
    const float px = g_new_xyz[(size_t)p*3], py = g_new_xyz[(size_t)p*3+1],
                pz = g_new_xyz[(size_t)p*3+2];
    const float pn = fmaf(px,px, fmaf(py,py, pz*pz));

    const float R0 = 0.8f*0.8f, R1 = 1.6f*1.6f;
    int* l1 = idx1s[w];
    int* l0 = idx0s[w];
    int c0 = 0, c1 = 0;
    const unsigned lt = (1u << lane) - 1u;
    for (int base = 0; base < KKEY; base += 32) {
        int k = base + lane;
        float4 kk = kp4[k];
        float dot = fmaf(px,kk.x, fmaf(py,kk.y, pz*kk.z));
        float d2  = fmaf(-2.f, dot, pn + kk.w);
        bool v1 = d2 < R1, v0 = d2 < R0;
        unsigned m1 = __ballot_sync(0xffffffffu, v1);
        unsigned m0 = __ballot_sync(0xffffffffu, v0);
        if (c1 < 32 && m1) {
            if (v1) { int rk = c1 + __popc(m1 & lt); if (rk < 32) l1[rk] = k; }
            c1 = min(32, c1 + __popc(m1));
        }
        if (c0 < 16 && m0) {
            if (v0) { int rk = c0 + __popc(m0 & lt); if (rk < 16) l0[rk] = k; }
            c0 = min(16, c0 + __popc(m0));
        }
        if (c0 >= 16 && c1 >= 32) break;
    }
    __syncwarp();
    if (c1 == 0) { if (lane == 0) l1[0] = 0; c1 = 1; }
    if (c0 == 0) { if (lane == 0) l0[0] = 0; c0 = 1; }
    __syncwarp();
    {
        int f1 = l1[0], f0 = l0[0];
        if (lane >= c1) l1[lane] = f1;
        if (lane < 16 && lane >= c0) l0[lane] = f0;
    }
    __syncwarp();

    {
        int k = l1[lane];
        float4 kk = kp4[k];
        g_rel1[(size_t)p*32 + lane] =
            make_float4(kk.x-px, kk.y-py, kk.z-pz, __int_as_float(k));
        if (lane < 16) {
            int k0 = l0[lane];
            float4 k4 = kp4[k0];
            g_rel0[(size_t)p*16 + lane] =
                make_float4(k4.x-px, k4.y-py, k4.z-pz, __int_as_float(k0));
        }
    }
}

// ---------------- kernel C2: 1 pt/warp, 128-bit smem, direct epilogue -------
// (R11/R14/R15 kC2 verbatim — validated at 105.8-107.8us)
#define KC2_SMEM_WORDS 27008
#define OFF2_WXYZ 10240
#define OFF2_B0   10624
#define OFF2_B1   10752
#define OFF2_HW   10880
#define OFF2_REL  24704
#define HW_PITCH  144

__global__ void __launch_bounds__(384, 2) kC2(
    const float* __restrict__ w00, const float* __restrict__ b00,
    const float* __restrict__ w01, const float* __restrict__ b01,
    const float* __restrict__ w10, const float* __restrict__ b10,
    const float* __restrict__ w11, const float* __restrict__ b11)
{
    extern __shared__ float sm[];
    uint2*    wpk  = (uint2*)sm;               // [sc][kt][lane][nt pad10]
    float*    wxyz = sm + OFF2_WXYZ;
    float*    b0s  = sm + OFF2_B0;
    float*    b1s  = sm + OFF2_B1;
    unsigned* hwg  = (unsigned*)(sm + OFF2_HW);
    float4*   relg = (float4*)(sm + OFF2_REL);

    for (int i = threadIdx.x; i < 2*8*32*8; i += 384) {
        int nt = i & 7, lane2 = (i >> 3) & 31, kt = (i >> 8) & 7, sc = i >> 11;
        int gid2 = lane2 >> 2, tig2 = lane2 & 3;
        const float* W1 = sc ? w11 : w01;
        int o = nt*8 + gid2;
        int j = kt*4 + tig2;
        wpk[sc*2560 + kt*320 + lane2*10 + nt] =
            make_uint2(f2tf32(W1[o*64 + j]), f2tf32(W1[o*64 + j + 32]));
    }
    for (int i = threadIdx.x; i < 2*3*64; i += 384) {
        int sc = i / 192, t = i % 192, d = t / 64, o = t % 64;
        wxyz[i] = (sc ? w10 : w00)[o*131 + d];
    }
    if (threadIdx.x < 256) {
        int sc = (threadIdx.x >> 6) & 1, o = threadIdx.x & 63;
        if (threadIdx.x < 128) b0s[threadIdx.x] = (sc ? b10 : b00)[o];
        else                   b1s[threadIdx.x - 128] = (sc ? b11 : b01)[o];
    }
    __syncthreads();

    const int w = threadIdx.x >> 5, lane = threadIdx.x & 31;
    const int gid = lane >> 2, tig = lane & 3;
    const int p  = blockIdx.x*12 + w;
    const int b  = p / NPTS;
    const int rp = p % NPTS;
    const int n  = rp / M_GRID, mm = rp % M_GRID;

    unsigned* hw = hwg + w*8*HW_PITCH;
    float4*   relw = relg + w*48;
    const int colu = gid*16 + tig*4;

    relw[16 + lane] = g_rel1[(size_t)p*32 + lane];
    if (lane < 16) relw[lane] = g_rel0[(size_t)p*16 + lane];
    __syncwarp();

    #pragma unroll
    for (int sc = 0; sc < 2; sc++) {
        const int NPASS = sc ? 2 : 1;
        const float* preb = g_pre + ((size_t)(sc*2 + b)*KKEY << 6);
        const uint2* wps = wpk + sc*2560;
        const float* wx = wxyz + sc*192;
        const float bias0a = b0s[sc*64 + lane],  bias0b = b0s[sc*64 + lane + 32];
        const float wxa0 = wx[lane],    wxa1 = wx[64+lane],  wxa2 = wx[128+lane];
        const float wxb0 = wx[lane+32], wxb1 = wx[96+lane],  wxb2 = wx[160+lane];

        float cm0[8], cm1[8];
        #pragma unroll
        for (int nt = 0; nt < 8; nt++) { cm0[nt] = -3.4e38f; cm1[nt] = -3.4e38f; }

        for (int pass = 0; pass < NPASS; pass++) {
            const float4* relb = sc ? (relw + 16 + pass*16) : relw;
            // ---- layer 0: 16 samples, row-paired (s, s+8), STS.128 ----
            #pragma unroll
            for (int sb = 0; sb < 8; sb += 2) {
                float4 rv[4];
                float2 pr[4];
                #pragma unroll
                for (int q = 0; q < 4; q++) {
                    int si = sb + (q & 1) + ((q >> 1) << 3);
                    rv[q] = relb[si];
                    int k = __float_as_int(rv[q].w);
                    pr[q] = *(const float2*)(preb + ((size_t)k << 6) + (lane << 1));
                }
                unsigned va[4], vb[4];
                #pragma unroll
                for (int q = 0; q < 4; q++) {
                    float a = pr[q].x + bias0a;
                    a = fmaf(rv[q].x, wxa0, a);
                    a = fmaf(rv[q].y, wxa1, a);
                    a = fmaf(rv[q].z, wxa2, a);
                    float bv = pr[q].y + bias0b;
                    bv = fmaf(rv[q].x, wxb0, bv);
                    bv = fmaf(rv[q].y, wxb1, bv);
                    bv = fmaf(rv[q].z, wxb2, bv);
                    va[q] = f2tf32(fmaxf(a, 0.f));
                    vb[q] = f2tf32(fmaxf(bv, 0.f));
                }
                *(uint4*)(hw + (sb  )*HW_PITCH + colu) =
                    make_uint4(va[0], va[2], vb[0], vb[2]);
                *(uint4*)(hw + (sb+1)*HW_PITCH + colu) =
                    make_uint4(va[1], va[3], vb[1], vb[3]);
            }
            __syncwarp();

            // ---- layer 1 MMA: a = 1 LDS.128, b = 4 LDS.128 per kt ----
            float acc[8][4];
            #pragma unroll
            for (int nt = 0; nt < 8; nt++)
                acc[nt][0] = acc[nt][1] = acc[nt][2] = acc[nt][3] = 0.f;
            #pragma unroll
            for (int kt = 0; kt < 8; kt++) {
                uint4 af = *(const uint4*)(hw + gid*HW_PITCH + kt*16 + tig*4);
                const uint2* wk = wps + kt*320 + lane*10;
                #pragma unroll
                for (int ntp = 0; ntp < 4; ntp++) {
                    uint4 bp = *(const uint4*)(wk + ntp*2);
                    mma_tf32(acc[2*ntp],   af.x, af.y, af.z, af.w, bp.x, bp.y);
                    mma_tf32(acc[2*ntp+1], af.x, af.y, af.z, af.w, bp.z, bp.w);
                }
            }
            #pragma unroll
            for (int nt = 0; nt < 8; nt++) {
                cm0[nt] = fmaxf(cm0[nt], fmaxf(acc[nt][0], acc[nt][2]));
                cm1[nt] = fmaxf(cm1[nt], fmaxf(acc[nt][1], acc[nt][3]));
            }
            __syncwarp();
        }

        // reduce across row-groups (lane bits 2..4)
        #pragma unroll
        for (int off = 4; off <= 16; off <<= 1) {
            #pragma unroll
            for (int nt = 0; nt < 8; nt++) {
                cm0[nt] = fmaxf(cm0[nt], __shfl_xor_sync(0xffffffffu, cm0[nt], off));
                cm1[nt] = fmaxf(cm1[nt], __shfl_xor_sync(0xffffffffu, cm1[nt], off));
            }
        }
        size_t rowb = (size_t)(b*NPROP + n)*QDIM + (size_t)sc*64*M_GRID + mm;
        if (gid == 0) {
            #pragma unroll
            for (int nt = 0; nt < 8; nt++) {
                int o0 = nt*8 + tig*2;
                float v0 = fmaxf(cm0[nt] + b1s[sc*64 + o0],     0.f);
                float v1 = fmaxf(cm1[nt] + b1s[sc*64 + o0 + 1], 0.f);
                g_pooled[rowb + (size_t)o0*M_GRID]     = v0;
                g_pooled[rowb + (size_t)(o0+1)*M_GRID] = v1;
            }
        }
    }
}

// ---------------- kernel D: K-split tf32 MMA, double-buffered 32-k tiles ----
// Dynamic smem: 2 buffers x (xs 96x40 + ws 64x40) = 51.2KB. One sync per tile.
#define KD_KT 32
#define XDP 40
#define KD_XWORDS (96*XDP)
#define KD_WWORDS (64*XDP)
#define KD_SMEM_BYTES (2*(KD_XWORDS + KD_WWORDS)*4)
__global__ void __launch_bounds__(384) kD(const float* __restrict__ w0) {
    extern __shared__ unsigned dsm[];
    unsigned* xsb = dsm;                       // 2 x KD_XWORDS
    unsigned* wsb = dsm + 2*KD_XWORDS;         // 2 x KD_WWORDS
    const int tid = threadIdx.x;
    const int w = tid >> 5, lane = tid & 31;
    const int gid = lane >> 2, tig = lane & 3;
    const int rg = w % 6, cg = w / 6;
    const int colbase = blockIdx.x * 64;
    const int kg0 = blockIdx.y * KCHUNK;

    const int frow = tid >> 2;
    const int fq   = (tid & 3) << 2;
    const int slotb = ((fq & 4) << 1) + (fq >> 3);

    const float* xg = g_pooled + (size_t)frow*QDIM + kg0 + fq;
    const float* wg = w0 + (size_t)(colbase + (tid >> 2))*QDIM + kg0 + ((tid & 3) << 2);

    float4 xv0 = *(const float4*)xg;
    float4 xv1 = *(const float4*)(xg + 16);
    float4 wv0 = make_float4(0.f,0.f,0.f,0.f), wv1 = wv0;
    if (tid < 256) { wv0 = *(const float4*)wg; wv1 = *(const float4*)(wg + 16); }

    float acc[4][4] = {};
    const int NT = KCHUNK / KD_KT;              // 12
    for (int t = 0; t < NT; t++) {
        unsigned* xs = xsb + (t & 1)*KD_XWORDS;
        unsigned* ws = wsb + (t & 1)*KD_WWORDS;
        {
            unsigned* d = xs + frow*XDP + slotb;
            d[0]  = f2tf32(xv0.x); d[2]  = f2tf32(xv0.y);
            d[4]  = f2tf32(xv0.z); d[6]  = f2tf32(xv0.w);
            d[20] = f2tf32(xv1.x); d[22] = f2tf32(xv1.y);
            d[24] = f2tf32(xv1.z); d[26] = f2tf32(xv1.w);
        }
        if (tid < 256) {
            unsigned* d = ws + (tid >> 2)*XDP + slotb;
            d[0]  = f2tf32(wv0.x); d[2]  = f2tf32(wv0.y);
            d[4]  = f2tf32(wv0.z); d[6]  = f2tf32(wv0.w);
            d[20] = f2tf32(wv1.x); d[22] = f2tf32(wv1.y);
            d[24] = f2tf32(wv1.z); d[26] = f2tf32(wv1.w);
        }
        __syncthreads();
        if (t + 1 < NT) {
            int dlt = (t + 1) * KD_KT;
            xv0 = *(const float4*)(xg + dlt);
            xv1 = *(const float4*)(xg + dlt + 16);
            if (tid < 256) {
                wv0 = *(const float4*)(wg + dlt);
                wv1 = *(const float4*)(wg + dlt + 16);
            }
        }
        #pragma unroll
        for (int kt = 0; kt < 4; kt++) {
            int off = (kt >> 1)*20 + (kt & 1)*8 + tig*2;
            uint2 alo = *(const uint2*)(xs + (rg*16 + gid    )*XDP + off);
            uint2 ahi = *(const uint2*)(xs + (rg*16 + gid + 8)*XDP + off);
            #pragma unroll
            for (int nt = 0; nt < 4; nt++) {
                uint2 bb = *(const uint2*)(ws + (cg*32 + nt*8 + gid)*XDP + off);
                mma_tf32(acc[nt], alo.x, ahi.x, alo.y, ahi.y, bb.x, bb.y);
            }
        }
    }
    #pragma unroll
    for (int nt = 0; nt < 4; nt++) {
        int col = colbase + cg*32 + nt*8 + tig*2;
        int row = rg*16 + gid;
        float* pp = g_partial + ((size_t)blockIdx.y*96 + row)*256 + col;
        *(float2*)pp             = make_float2(acc[nt][0], acc[nt][1]);
        *(float2*)(pp + 8*256)   = make_float2(acc[nt][2], acc[nt][3]);
    }
}

// ---------------- kernel E: parallel reduce + relu + 256x256 GEMM + relu ----
__global__ void __launch_bounds__(1024) kE(const float* __restrict__ rb0,
                                           const float* __restrict__ rw1,
                                           const float* __restrict__ rb1,
                                           float* __restrict__ out) {
    __shared__ float hpart[4][256];
    __shared__ float h2s[256];
    __shared__ float w1s[256*33];
    const int row = blockIdx.x;
    const int o = threadIdx.x & 255, q = threadIdx.x >> 8;

    float s = 0.f;
    #pragma unroll 6
    for (int i = 0; i < 18; i++) {
        int ks = q*18 + i;
        s += g_partial[((size_t)ks*96 + row)*256 + o];
    }
    hpart[q][o] = s;
    __syncthreads();
    if (threadIdx.x < 256) {
        float t = rb0[o] + ((hpart[0][o] + hpart[1][o]) + (hpart[2][o] + hpart[3][o]));
        h2s[o] = fmaxf(t, 0.f);
    }
    __syncthreads();

    float acc = (threadIdx.x < 256) ? rb1[o] : 0.f;
    for (int jt = 0; jt < 256; jt += 32) {
        for (int i = threadIdx.x; i < 8192; i += 1024) {
            int oo = i >> 5, jj = i & 31;
            w1s[oo*33 + jj] = rw1[(size_t)oo*256 + jt + jj];
        }
        __syncthreads();
        if (threadIdx.x < 256) {
            #pragma unroll
            for (int jj = 0; jj < 32; jj++)
                acc = fmaf(h2s[jt + jj], w1s[o*33 + jj], acc);
        }
        __syncthreads();
    }
    if (threadIdx.x < 256)
        out[(size_t)row*256 + o] = fmaxf(acc, 0.f);
}

// ---------------- launch ----------------
extern "C" void kernel_launch(void* const* d_in, const int* in_sizes, int n_in,
                              void* d_out, int out_size) {
    const float* proposals = (const float*)d_in[0];
    const float* kxyz      = (const float*)d_in[1];
    const float* kfeat     = (const float*)d_in[2];
    const float* gnoise    = (const float*)d_in[3];
    const float* w00 = (const float*)d_in[4];
    const float* b00 = (const float*)d_in[5];
    const float* w01 = (const float*)d_in[6];
    const float* b01 = (const float*)d_in[7];
    const float* w10 = (const float*)d_in[8];
    const float* b10 = (const float*)d_in[9];
    const float* w11 = (const float*)d_in[10];
    const float* b11 = (const float*)d_in[11];
    const float* rw0 = (const float*)d_in[12];
    const float* rb0 = (const float*)d_in[13];
    const float* rw1 = (const float*)d_in[14];
    const float* rb1 = (const float*)d_in[15];
    float* out = (float*)d_out;

    cudaFuncSetAttribute(kC2, cudaFuncAttributeMaxDynamicSharedMemorySize,
                         KC2_SMEM_WORDS * 4);
    cudaFuncSetAttribute(kD, cudaFuncAttributeMaxDynamicSharedMemorySize,
                         KD_SMEM_BYTES);

    kA<<<(NTOT + 255)/256, 256>>>(proposals, gnoise);
    kB<<<dim3(KKEY/32, 4), 256>>>(kfeat, w00, w10);
    kQ<<<NTOT/32, 1024>>>(kxyz);
    kC2<<<NTOT/12, 384, KC2_SMEM_WORDS * 4>>>(w00, b00, w01, b01,
                                              w10, b10, w11, b11);
    kD<<<dim3(4, KSPLIT), 384, KD_SMEM_BYTES>>>(rw0);
    kE<<<96, 1024>>>(rb0, rw1, rb1, out);
}

// round 17
// speedup vs baseline: 1.1551x; 1.0004x over previous
#include <cuda_runtime.h>
#include <math.h>

#define KKEY   2048
#define CFEAT  128
#define M_GRID 216
#define NPROP  48
#define NPTS   (NPROP*M_GRID)      // 10368 per batch
#define NTOT   (2*NPTS)            // 20736
#define QDIM   (128*M_GRID)        // 27648
#define KSPLIT 72
#define KCHUNK 384

typedef unsigned long long ull;

__device__ __forceinline__ ull pack2(float lo, float hi) {
    ull r; asm("mov.b64 %0, {%1, %2};" : "=l"(r) : "f"(lo), "f"(hi)); return r;
}
__device__ __forceinline__ ull ffma2(ull a, ull b, ull c) {
    ull d; asm("fma.rn.f32x2 %0, %1, %2, %3;" : "=l"(d) : "l"(a), "l"(b), "l"(c)); return d;
}
__device__ __forceinline__ float2 unpack2(ull v) {
    float2 f; asm("mov.b64 {%0, %1}, %2;" : "=f"(f.x), "=f"(f.y) : "l"(v)); return f;
}
__device__ __forceinline__ unsigned f2tf32(float v) {
    unsigned u; asm("cvt.rna.tf32.f32 %0, %1;" : "=r"(u) : "f"(v)); return u;
}
__device__ __forceinline__ void mma_tf32(float d[4], const unsigned a0, const unsigned a1,
                                         const unsigned a2, const unsigned a3,
                                         const unsigned b0, const unsigned b1) {
    asm("mma.sync.aligned.m16n8k8.row.col.f32.tf32.tf32.f32 "
        "{%0,%1,%2,%3}, {%4,%5,%6,%7}, {%8,%9}, {%0,%1,%2,%3};"
        : "+f"(d[0]), "+f"(d[1]), "+f"(d[2]), "+f"(d[3])
        : "r"(a0), "r"(a1), "r"(a2), "r"(a3), "r"(b0), "r"(b1));
}

// ---------------- scratch ----------------
__device__ float  g_new_xyz[NTOT*3];
__device__ float  g_pre[2*2*KKEY*64];        // [scale][b][k][interleaved o]
__device__ float4 g_rel1[NTOT*32];           // {rx,ry,rz, bitcast k}
__device__ float4 g_rel0[NTOT*16];
__device__ float  g_pooled[2*NPROP*QDIM];    // 96 x 27648, q = co*216+mm
__device__ float  g_partial[KSPLIT*96*256];

// ---------------- kernel A: grid transform -> new_xyz ----------------
__global__ void __launch_bounds__(256) kA(const float* __restrict__ prop,
                                          const float* __restrict__ gnoise) {
    int t = blockIdx.x*256 + threadIdx.x;
    if (t >= NTOT) return;
    int b = t / NPTS, r = t % NPTS;
    int n = r / M_GRID, mm = r % M_GRID;
    const float* p = prop + (size_t)(b*NPROP + n)*7;
    const float* g = gnoise + ((size_t)(b*NPROP + n)*M_GRID + mm)*3;
    float gx = g[0]*p[3], gy = g[1]*p[4], gz = g[2]*p[5];
    float c = cosf(p[6]), s = sinf(p[6]);
    float* o = g_new_xyz + (size_t)t*3;
    o[0] = c*gx - s*gy + p[0];
    o[1] = s*gx + c*gy + p[1];
    o[2] = gz + p[2];
}

// ---------------- kernel B: pre[k][o] = W0[:,3:] . feats[:,k] ----------------
__global__ void __launch_bounds__(256) kB(const float* __restrict__ feats,
                                          const float* __restrict__ w0,
                                          const float* __restrict__ w1) {
    __shared__ float Ws[CFEAT*64];
    __shared__ float fs[CFEAT*32];
    int sb = blockIdx.y; int sc = sb >> 1, b = sb & 1;
    const float* W = sc ? w1 : w0;
    for (int i = threadIdx.x; i < CFEAT*64; i += 256) {
        int c = i >> 6, o = i & 63;
        Ws[i] = W[o*131 + 3 + c];
    }
    int kbase = blockIdx.x * 32;
    const float* fb = feats + (size_t)b*CFEAT*KKEY + kbase;
    for (int i = threadIdx.x; i < CFEAT*8; i += 256) {
        int c = i >> 3, q = i & 7;
        *(float4*)(fs + c*32 + q*4) = *(const float4*)(fb + (size_t)c*KKEY + q*4);
    }
    __syncthreads();

    int o  = threadIdx.x & 63;
    int kk = threadIdx.x >> 6;
    ull acc0 = 0, acc1 = 0, acc2 = 0, acc3 = 0;
    #pragma unroll 4
    for (int c = 0; c < CFEAT; c++) {
        float w = Ws[c*64 + o];
        ull wd = pack2(w, w);
        const ull* f = (const ull*)(fs + c*32 + kk*8);
        acc0 = ffma2(wd, f[0], acc0);
        acc1 = ffma2(wd, f[1], acc1);
        acc2 = ffma2(wd, f[2], acc2);
        acc3 = ffma2(wd, f[3], acc3);
    }
    size_t base = ((size_t)(sc*2 + b)*KKEY + kbase + kk*8) << 6;
    int oi = ((o & 31) << 1) + (o >> 5);
    float2 u;
    u = unpack2(acc0); g_pre[base + oi] = u.x; g_pre[base + 64 + oi] = u.y;
    u = unpack2(acc1); g_pre[base + 128 + oi] = u.x; g_pre[base + 192 + oi] = u.y;
    u = unpack2(acc2); g_pre[base + 256 + oi] = u.x; g_pre[base + 320 + oi] = u.y;
    u = unpack2(acc3); g_pre[base + 384 + oi] = u.x; g_pre[base + 448 + oi] = u.y;
}

// ---------------- kernel Q: ball query -> padded idx + rel coords ----------
// 512 threads = 16 points/block (3 blocks/SM co-resident -> tail warps overlap)
// scan unrolled x2: two kp4 loads in flight, one exit-check per 64 keypoints
__global__ void __launch_bounds__(512) kQ(const float* __restrict__ kxyzg) {
    __shared__ float4 kp4[KKEY];               // {x,y,z,|k|^2}, 32KB
    __shared__ int idx1s[16][32], idx0s[16][16];

    const int b = blockIdx.x / 648;
    const float* kb = kxyzg + (size_t)b*KKEY*3;
    for (int i = threadIdx.x; i < KKEY; i += 512) {
        float x = kb[i*3], y = kb[i*3+1], z = kb[i*3+2];
        kp4[i] = make_float4(x, y, z, fmaf(x,x, fmaf(y,y, z*z)));
    }
    __syncthreads();

    const int w = threadIdx.x >> 5, lane = threadIdx.x & 31;
    const int p = blockIdx.x*16 + w;
    const float px = g_new_xyz[(size_t)p*3], py = g_new_xyz[(size_t)p*3+1],
                pz = g_new_xyz[(size_t)p*3+2];
    const float pn = fmaf(px,px, fmaf(py,py, pz*pz));

    const float R0 = 0.8f*0.8f, R1 = 1.6f*1.6f;
    int* l1 = idx1s[w];
    int* l0 = idx0s[w];
    int c0 = 0, c1 = 0;
    const unsigned lt = (1u << lane) - 1u;
    for (int base = 0; base < KKEY; base += 64) {
        int ka = base + lane, kc = base + 32 + lane;
        float4 va4 = kp4[ka];
        float4 vb4 = kp4[kc];
        float dota = fmaf(px,va4.x, fmaf(py,va4.y, pz*va4.z));
        float d2a  = fmaf(-2.f, dota, pn + va4.w);
        float dotb = fmaf(px,vb4.x, fmaf(py,vb4.y, pz*vb4.z));
        float d2b  = fmaf(-2.f, dotb, pn + vb4.w);

        // group base (processed first: preserves index ordering)
        {
            bool v1 = d2a < R1, v0 = d2a < R0;
            unsigned m1 = __ballot_sync(0xffffffffu, v1);
            unsigned m0 = __ballot_sync(0xffffffffu, v0);
            if (c1 < 32 && m1) {
                if (v1) { int rk = c1 + __popc(m1 & lt); if (rk < 32) l1[rk] = ka; }
                c1 = min(32, c1 + __popc(m1));
            }
            if (c0 < 16 && m0) {
                if (v0) { int rk = c0 + __popc(m0 & lt); if (rk < 16) l0[rk] = ka; }
                c0 = min(16, c0 + __popc(m0));
            }
        }
        // group base+32
        {
            bool v1 = d2b < R1, v0 = d2b < R0;
            unsigned m1 = __ballot_sync(0xffffffffu, v1);
            unsigned m0 = __ballot_sync(0xffffffffu, v0);
            if (c1 < 32 && m1) {
                if (v1) { int rk = c1 + __popc(m1 & lt); if (rk < 32) l1[rk] = kc; }
                c1 = min(32, c1 + __popc(m1));
            }
            if (c0 < 16 && m0) {
                if (v0) { int rk = c0 + __popc(m0 & lt); if (rk < 16) l0[rk] = kc; }
                c0 = min(16, c0 + __popc(m0));
            }
        }
        if (c0 >= 16 && c1 >= 32) break;
    }
    __syncwarp();
    if (c1 == 0) { if (lane == 0) l1[0] = 0; c1 = 1; }
    if (c0 == 0) { if (lane == 0) l0[0] = 0; c0 = 1; }
    __syncwarp();
    {
        int f1 = l1[0], f0 = l0[0];
        if (lane >= c1) l1[lane] = f1;
        if (lane < 16 && lane >= c0) l0[lane] = f0;
    }
    __syncwarp();

    {
        int k = l1[lane];
        float4 kk = kp4[k];
        g_rel1[(size_t)p*32 + lane] =
            make_float4(kk.x-px, kk.y-py, kk.z-pz, __int_as_float(k));
        if (lane < 16) {
            int k0 = l0[lane];
            float4 k4 = kp4[k0];
            g_rel0[(size_t)p*16 + lane] =
                make_float4(k4.x-px, k4.y-py, k4.z-pz, __int_as_float(k0));
        }
    }
}

// ---------------- kernel C2: 1 pt/warp, 128-bit smem, direct epilogue -------
// (R11/R14/R15/R16 kC2 verbatim — validated at 105.8-107.8us)
#define KC2_SMEM_WORDS 27008
#define OFF2_WXYZ 10240
#define OFF2_B0   10624
#define OFF2_B1   10752
#define OFF2_HW   10880
#define OFF2_REL  24704
#define HW_PITCH  144

__global__ void __launch_bounds__(384, 2) kC2(
    const float* __restrict__ w00, const float* __restrict__ b00,
    const float* __restrict__ w01, const float* __restrict__ b01,
    const float* __restrict__ w10, const float* __restrict__ b10,
    const float* __restrict__ w11, const float* __restrict__ b11)
{
    extern __shared__ float sm[];
    uint2*    wpk  = (uint2*)sm;               // [sc][kt][lane][nt pad10]
    float*    wxyz = sm + OFF2_WXYZ;
    float*    b0s  = sm + OFF2_B0;
    float*    b1s  = sm + OFF2_B1;
    unsigned* hwg  = (unsigned*)(sm + OFF2_HW);
    float4*   relg = (float4*)(sm + OFF2_REL);

    for (int i = threadIdx.x; i < 2*8*32*8; i += 384) {
        int nt = i & 7, lane2 = (i >> 3) & 31, kt = (i >> 8) & 7, sc = i >> 11;
        int gid2 = lane2 >> 2, tig2 = lane2 & 3;
        const float* W1 = sc ? w11 : w01;
        int o = nt*8 + gid2;
        int j = kt*4 + tig2;
        wpk[sc*2560 + kt*320 + lane2*10 + nt] =
            make_uint2(f2tf32(W1[o*64 + j]), f2tf32(W1[o*64 + j + 32]));
    }
    for (int i = threadIdx.x; i < 2*3*64; i += 384) {
        int sc = i / 192, t = i % 192, d = t / 64, o = t % 64;
        wxyz[i] = (sc ? w10 : w00)[o*131 + d];
    }
    if (threadIdx.x < 256) {
        int sc = (threadIdx.x >> 6) & 1, o = threadIdx.x & 63;
        if (threadIdx.x < 128) b0s[threadIdx.x] = (sc ? b10 : b00)[o];
        else                   b1s[threadIdx.x - 128] = (sc ? b11 : b01)[o];
    }
    __syncthreads();

    const int w = threadIdx.x >> 5, lane = threadIdx.x & 31;
    const int gid = lane >> 2, tig = lane & 3;
    const int p  = blockIdx.x*12 + w;
    const int b  = p / NPTS;
    const int rp = p % NPTS;
    const int n  = rp / M_GRID, mm = rp % M_GRID;

    unsigned* hw = hwg + w*8*HW_PITCH;
    float4*   relw = relg + w*48;
    const int colu = gid*16 + tig*4;

    relw[16 + lane] = g_rel1[(size_t)p*32 + lane];
    if (lane < 16) relw[lane] = g_rel0[(size_t)p*16 + lane];
    __syncwarp();

    #pragma unroll
    for (int sc = 0; sc < 2; sc++) {
        const int NPASS = sc ? 2 : 1;
        const float* preb = g_pre + ((size_t)(sc*2 + b)*KKEY << 6);
        const uint2* wps = wpk + sc*2560;
        const float* wx = wxyz + sc*192;
        const float bias0a = b0s[sc*64 + lane],  bias0b = b0s[sc*64 + lane + 32];
        const float wxa0 = wx[lane],    wxa1 = wx[64+lane],  wxa2 = wx[128+lane];
        const float wxb0 = wx[lane+32], wxb1 = wx[96+lane],  wxb2 = wx[160+lane];

        float cm0[8], cm1[8];
        #pragma unroll
        for (int nt = 0; nt < 8; nt++) { cm0[nt] = -3.4e38f; cm1[nt] = -3.4e38f; }

        for (int pass = 0; pass < NPASS; pass++) {
            const float4* relb = sc ? (relw + 16 + pass*16) : relw;
            // ---- layer 0: 16 samples, row-paired (s, s+8), STS.128 ----
            #pragma unroll
            for (int sb = 0; sb < 8; sb += 2) {
                float4 rv[4];
                float2 pr[4];
                #pragma unroll
                for (int q = 0; q < 4; q++) {
                    int si = sb + (q & 1) + ((q >> 1) << 3);
                    rv[q] = relb[si];
                    int k = __float_as_int(rv[q].w);
                    pr[q] = *(const float2*)(preb + ((size_t)k << 6) + (lane << 1));
                }
                unsigned va[4], vb[4];
                #pragma unroll
                for (int q = 0; q < 4; q++) {
                    float a = pr[q].x + bias0a;
                    a = fmaf(rv[q].x, wxa0, a);
                    a = fmaf(rv[q].y, wxa1, a);
                    a = fmaf(rv[q].z, wxa2, a);
                    float bv = pr[q].y + bias0b;
                    bv = fmaf(rv[q].x, wxb0, bv);
                    bv = fmaf(rv[q].y, wxb1, bv);
                    bv = fmaf(rv[q].z, wxb2, bv);
                    va[q] = f2tf32(fmaxf(a, 0.f));
                    vb[q] = f2tf32(fmaxf(bv, 0.f));
                }
                *(uint4*)(hw + (sb  )*HW_PITCH + colu) =
                    make_uint4(va[0], va[2], vb[0], vb[2]);
                *(uint4*)(hw + (sb+1)*HW_PITCH + colu) =
                    make_uint4(va[1], va[3], vb[1], vb[3]);
            }
            __syncwarp();

            // ---- layer 1 MMA: a = 1 LDS.128, b = 4 LDS.128 per kt ----
            float acc[8][4];
            #pragma unroll
            for (int nt = 0; nt < 8; nt++)
                acc[nt][0] = acc[nt][1] = acc[nt][2] = acc[nt][3] = 0.f;
            #pragma unroll
            for (int kt = 0; kt < 8; kt++) {
                uint4 af = *(const uint4*)(hw + gid*HW_PITCH + kt*16 + tig*4);
                const uint2* wk = wps + kt*320 + lane*10;
                #pragma unroll
                for (int ntp = 0; ntp < 4; ntp++) {
                    uint4 bp = *(const uint4*)(wk + ntp*2);
                    mma_tf32(acc[2*ntp],   af.x, af.y, af.z, af.w, bp.x, bp.y);
                    mma_tf32(acc[2*ntp+1], af.x, af.y, af.z, af.w, bp.z, bp.w);
                }
            }
            #pragma unroll
            for (int nt = 0; nt < 8; nt++) {
                cm0[nt] = fmaxf(cm0[nt], fmaxf(acc[nt][0], acc[nt][2]));
                cm1[nt] = fmaxf(cm1[nt], fmaxf(acc[nt][1], acc[nt][3]));
            }
            __syncwarp();
        }

        // reduce across row-groups (lane bits 2..4)
        #pragma unroll
        for (int off = 4; off <= 16; off <<= 1) {
            #pragma unroll
            for (int nt = 0; nt < 8; nt++) {
                cm0[nt] = fmaxf(cm0[nt], __shfl_xor_sync(0xffffffffu, cm0[nt], off));
                cm1[nt] = fmaxf(cm1[nt], __shfl_xor_sync(0xffffffffu, cm1[nt], off));
            }
        }
        size_t rowb = (size_t)(b*NPROP + n)*QDIM + (size_t)sc*64*M_GRID + mm;
        if (gid == 0) {
            #pragma unroll
            for (int nt = 0; nt < 8; nt++) {
                int o0 = nt*8 + tig*2;
                float v0 = fmaxf(cm0[nt] + b1s[sc*64 + o0],     0.f);
                float v1 = fmaxf(cm1[nt] + b1s[sc*64 + o0 + 1], 0.f);
                g_pooled[rowb + (size_t)o0*M_GRID]     = v0;
                g_pooled[rowb + (size_t)(o0+1)*M_GRID] = v1;
            }
        }
    }
}

// ---------------- kernel D: K-split tf32 MMA, double-buffered (R16) ---------
#define KD_KT 32
#define XDP 40
#define KD_XWORDS (96*XDP)
#define KD_WWORDS (64*XDP)
#define KD_SMEM_BYTES (2*(KD_XWORDS + KD_WWORDS)*4)
__global__ void __launch_bounds__(384) kD(const float* __restrict__ w0) {
    extern __shared__ unsigned dsm[];
    unsigned* xsb = dsm;
    unsigned* wsb = dsm + 2*KD_XWORDS;
    const int tid = threadIdx.x;
    const int w = tid >> 5, lane = tid & 31;
    const int gid = lane >> 2, tig = lane & 3;
    const int rg = w % 6, cg = w / 6;
    const int colbase = blockIdx.x * 64;
    const int kg0 = blockIdx.y * KCHUNK;

    const int frow = tid >> 2;
    const int fq   = (tid & 3) << 2;
    const int slotb = ((fq & 4) << 1) + (fq >> 3);

    const float* xg = g_pooled + (size_t)frow*QDIM + kg0 + fq;
    const float* wg = w0 + (size_t)(colbase + (tid >> 2))*QDIM + kg0 + ((tid & 3) << 2);

    float4 xv0 = *(const float4*)xg;
    float4 xv1 = *(const float4*)(xg + 16);
    float4 wv0 = make_float4(0.f,0.f,0.f,0.f), wv1 = wv0;
    if (tid < 256) { wv0 = *(const float4*)wg; wv1 = *(const float4*)(wg + 16); }

    float acc[4][4] = {};
    const int NT = KCHUNK / KD_KT;              // 12
    for (int t = 0; t < NT; t++) {
        unsigned* xs = xsb + (t & 1)*KD_XWORDS;
        unsigned* ws = wsb + (t & 1)*KD_WWORDS;
        {
            unsigned* d = xs + frow*XDP + slotb;
            d[0]  = f2tf32(xv0.x); d[2]  = f2tf32(xv0.y);
            d[4]  = f2tf32(xv0.z); d[6]  = f2tf32(xv0.w);
            d[20] = f2tf32(xv1.x); d[22] = f2tf32(xv1.y);
            d[24] = f2tf32(xv1.z); d[26] = f2tf32(xv1.w);
        }
        if (tid < 256) {
            unsigned* d = ws + (tid >> 2)*XDP + slotb;
            d[0]  = f2tf32(wv0.x); d[2]  = f2tf32(wv0.y);
            d[4]  = f2tf32(wv0.z); d[6]  = f2tf32(wv0.w);
            d[20] = f2tf32(wv1.x); d[22] = f2tf32(wv1.y);
            d[24] = f2tf32(wv1.z); d[26] = f2tf32(wv1.w);
        }
        __syncthreads();
        if (t + 1 < NT) {
            int dlt = (t + 1) * KD_KT;
            xv0 = *(const float4*)(xg + dlt);
            xv1 = *(const float4*)(xg + dlt + 16);
            if (tid < 256) {
                wv0 = *(const float4*)(wg + dlt);
                wv1 = *(const float4*)(wg + dlt + 16);
            }
        }
        #pragma unroll
        for (int kt = 0; kt < 4; kt++) {
            int off = (kt >> 1)*20 + (kt & 1)*8 + tig*2;
            uint2 alo = *(const uint2*)(xs + (rg*16 + gid    )*XDP + off);
            uint2 ahi = *(const uint2*)(xs + (rg*16 + gid + 8)*XDP + off);
            #pragma unroll
            for (int nt = 0; nt < 4; nt++) {
                uint2 bb = *(const uint2*)(ws + (cg*32 + nt*8 + gid)*XDP + off);
                mma_tf32(acc[nt], alo.x, ahi.x, alo.y, ahi.y, bb.x, bb.y);
            }
        }
    }
    #pragma unroll
    for (int nt = 0; nt < 4; nt++) {
        int col = colbase + cg*32 + nt*8 + tig*2;
        int row = rg*16 + gid;
        float* pp = g_partial + ((size_t)blockIdx.y*96 + row)*256 + col;
        *(float2*)pp             = make_float2(acc[nt][0], acc[nt][1]);
        *(float2*)(pp + 8*256)   = make_float2(acc[nt][2], acc[nt][3]);
    }
}

// ---------------- kernel E: parallel reduce + relu + 256x256 GEMM + relu ----
__global__ void __launch_bounds__(1024) kE(const float* __restrict__ rb0,
                                           const float* __restrict__ rw1,
                                           const float* __restrict__ rb1,
                                           float* __restrict__ out) {
    __shared__ float hpart[4][256];
    __shared__ float h2s[256];
    __shared__ float w1s[256*33];
    const int row = blockIdx.x;
    const int o = threadIdx.x & 255, q = threadIdx.x >> 8;

    float s = 0.f;
    #pragma unroll 6
    for (int i = 0; i < 18; i++) {
        int ks = q*18 + i;
        s += g_partial[((size_t)ks*96 + row)*256 + o];
    }
    hpart[q][o] = s;
    __syncthreads();
    if (threadIdx.x < 256) {
        float t = rb0[o] + ((hpart[0][o] + hpart[1][o]) + (hpart[2][o] + hpart[3][o]));
        h2s[o] = fmaxf(t, 0.f);
    }
    __syncthreads();

    float acc = (threadIdx.x < 256) ? rb1[o] : 0.f;
    for (int jt = 0; jt < 256; jt += 32) {
        for (int i = threadIdx.x; i < 8192; i += 1024) {
            int oo = i >> 5, jj = i & 31;
            w1s[oo*33 + jj] = rw1[(size_t)oo*256 + jt + jj];
        }
        __syncthreads();
        if (threadIdx.x < 256) {
            #pragma unroll
            for (int jj = 0; jj < 32; jj++)
                acc = fmaf(h2s[jt + jj], w1s[o*33 + jj], acc);
        }
        __syncthreads();
    }
    if (threadIdx.x < 256)
        out[(size_t)row*256 + o] = fmaxf(acc, 0.f);
}

// ---------------- launch ----------------
extern "C" void kernel_launch(void* const* d_in, const int* in_sizes, int n_in,
                              void* d_out, int out_size) {
    const float* proposals = (const float*)d_in[0];
    const float* kxyz      = (const float*)d_in[1];
    const float* kfeat     = (const float*)d_in[2];
    const float* gnoise    = (const float*)d_in[3];
    const float* w00 = (const float*)d_in[4];
    const float* b00 = (const float*)d_in[5];
    const float* w01 = (const float*)d_in[6];
    const float* b01 = (const float*)d_in[7];
    const float* w10 = (const float*)d_in[8];
    const float* b10 = (const float*)d_in[9];
    const float* w11 = (const float*)d_in[10];
    const float* b11 = (const float*)d_in[11];
    const float* rw0 = (const float*)d_in[12];
    const float* rb0 = (const float*)d_in[13];
    const float* rw1 = (const float*)d_in[14];
    const float* rb1 = (const float*)d_in[15];
    float* out = (float*)d_out;

    cudaFuncSetAttribute(kC2, cudaFuncAttributeMaxDynamicSharedMemorySize,
                         KC2_SMEM_WORDS * 4);
    cudaFuncSetAttribute(kD, cudaFuncAttributeMaxDynamicSharedMemorySize,
                         KD_SMEM_BYTES);

    kA<<<(NTOT + 255)/256, 256>>>(proposals, gnoise);
    kB<<<dim3(KKEY/32, 4), 256>>>(kfeat, w00, w10);
    kQ<<<NTOT/16, 512>>>(kxyz);
    kC2<<<NTOT/12, 384, KC2_SMEM_WORDS * 4>>>(w00, b00, w01, b01,
                                              w10, b10, w11, b11);
    kD<<<dim3(4, KSPLIT), 384, KD_SMEM_BYTES>>>(rw0);
    kE<<<96, 1024>>>(rb0, rw1, rb1, out);
}